// round 8
// baseline (speedup 1.0000x reference)
#include <cuda_runtime.h>
#include <math.h>

// ---------------------------------------------------------------------------
// SwinTransformerBlock3D — fp32, f32x2 FMA, rolling register prefetch of weights
// 2 kernels: A = LN1+gather+QKV+attn+proj+residual, B = LN2+MLP+residual
// ---------------------------------------------------------------------------

#define LTOK (16*64*64)
#define BATCH 2
#define C 96
#define NH 6
#define HD 16
#define NW 64
#define MLPH 384
#define NTILE 2048

typedef unsigned long long u64t;

__device__ float g_ybuf[(size_t)BATCH * LTOK * C];

// ---------------- helpers --------------------------------------------------
__device__ __forceinline__ unsigned sp(const void* p) {
    return (unsigned)__cvta_generic_to_shared(p);
}
__device__ __forceinline__ u64t ldsb64(const float* p) {
    u64t v; asm volatile("ld.shared.b64 %0,[%1];" : "=l"(v) : "r"(sp(p))); return v;
}
__device__ __forceinline__ void ldsv2b64(u64t& a, u64t& b, const float* p) {
    asm volatile("ld.shared.v2.b64 {%0,%1},[%2];" : "=l"(a), "=l"(b) : "r"(sp(p)));
}
__device__ __forceinline__ float2 ldsf2(const float* p) {
    float2 r; asm volatile("ld.shared.v2.f32 {%0,%1},[%2];"
                           : "=f"(r.x), "=f"(r.y) : "r"(sp(p))); return r;
}
__device__ __forceinline__ float4 ldsf4(const float* p) {
    float4 r; asm volatile("ld.shared.v4.f32 {%0,%1,%2,%3},[%4];"
                           : "=f"(r.x),"=f"(r.y),"=f"(r.z),"=f"(r.w) : "r"(sp(p))); return r;
}
__device__ __forceinline__ void stsb64(float* p, u64t v) {
    asm volatile("st.shared.b64 [%0],%1;" :: "r"(sp(p)), "l"(v));
}
__device__ __forceinline__ u64t pk2(float x, float y) {
    u64t r; asm("mov.b64 %0,{%1,%2};" : "=l"(r) : "f"(x), "f"(y)); return r;
}
__device__ __forceinline__ u64t dup2(float x) { return pk2(x, x); }
__device__ __forceinline__ float2 up2(u64t v) {
    float2 r; asm("mov.b64 {%0,%1},%2;" : "=f"(r.x), "=f"(r.y) : "l"(v)); return r;
}
__device__ __forceinline__ void fma2(u64t& d, u64t a, u64t b) {
    asm("fma.rn.f32x2 %0,%1,%2,%0;" : "+l"(d) : "l"(a), "l"(b));
}
__device__ __forceinline__ u64t ldg64(const float* p) {
    return __ldg((const u64t*)p);
}

// kernel A smem (float offsets)
#define A_XD   0        // xdup [96][130] dup pairs; reused as oT [96][68]
#define A_Q    12480    // qbuf [64][100]; reused as proj red [64][98]
#define A_KT   18880    // kT [96][68]
#define A_V    25408    // vbuf [64][100]
#define A_S    31808    // sbuf [64][68]
#define A_BIAS 36160    // 2058
#define A_REL  38218    // u16[4096]
#define A_SRC  40266    // int[64]
#define A_TOT  40330

// ===========================================================================
// Kernel A
// ===========================================================================
__global__ __launch_bounds__(512, 1)
void win_attn_kernel(const float* __restrict__ x,
                     const float* __restrict__ g1, const float* __restrict__ b1,
                     const float* __restrict__ qkv_w, const float* __restrict__ qkv_b,
                     const float* __restrict__ proj_w, const float* __restrict__ proj_b,
                     const float* __restrict__ bias_table)
{
    extern __shared__ float smf[];
    float* xdup = smf + A_XD;
    float* qbuf = smf + A_Q;
    float* kT   = smf + A_KT;
    float* vbuf = smf + A_V;
    float* sbuf = smf + A_S;
    float* sbias = smf + A_BIAS;
    unsigned short* rel = (unsigned short*)(smf + A_REL);
    int* srcidx = (int*)(smf + A_SRC);

    const int tid = threadIdx.x;
    const int wb = blockIdx.x;
    const int bb = wb >> 10;
    const int w  = wb & 1023;
    const int iw = w >> 8, xw = (w >> 4) & 15, tw = w & 15;

    if (tid < NW) {
        int i = tid >> 4, xx = (tid >> 2) & 3, tt = tid & 3;
        int gi = (iw * 4 + i  + 2) & 15;
        int gx = (xw * 4 + xx + 2) & 63;
        int gt = (tw * 4 + tt + 2) & 63;
        srcidx[tid] = ((gi << 6) + gx) * 64 + gt;
    }
    for (int p = tid; p < 4096; p += 512) {
        int n = p >> 6, m = p & 63;
        int di = (n >> 4)       - (m >> 4)       + 3;
        int dx = ((n >> 2) & 3) - ((m >> 2) & 3) + 3;
        int dt = (n & 3)        - (m & 3)        + 3;
        rel[p] = (unsigned short)((di * 7 + dx) * 7 + dt);
    }
    for (int i = tid; i < 343 * NH; i += 512) sbias[i] = __ldg(bias_table + i);
    __syncthreads();

    // ---- LN1 -> xdup[c][2n] dup pairs
    {
        const int n = tid >> 3, q8 = tid & 7;
        const float* xr = x + ((size_t)(bb * LTOK + srcidx[n])) * C + q8 * 12;
        float v[12]; float s = 0.f, ss = 0.f;
        #pragma unroll
        for (int j = 0; j < 12; j++) { float t = xr[j]; v[j] = t; s += t; ss += t * t; }
        s  += __shfl_xor_sync(0xffffffffu, s, 1);  ss += __shfl_xor_sync(0xffffffffu, ss, 1);
        s  += __shfl_xor_sync(0xffffffffu, s, 2);  ss += __shfl_xor_sync(0xffffffffu, ss, 2);
        s  += __shfl_xor_sync(0xffffffffu, s, 4);  ss += __shfl_xor_sync(0xffffffffu, ss, 4);
        float mean = s * (1.f / 96.f);
        float var  = ss * (1.f / 96.f) - mean * mean;
        float rstd = rsqrtf(var + 1e-5f);
        #pragma unroll
        for (int j = 0; j < 12; j++) {
            int c = q8 * 12 + j;
            float val = (v[j] - mean) * rstd * __ldg(g1 + c) + __ldg(b1 + c);
            stsb64(xdup + c * 130 + 2 * n, dup2(val));
        }
    }
    __syncthreads();

    // ---- QKV GEMM [64x96]@[96x288], rolling prefetch (distance 2)
    {
        const int rg = tid >> 5, lane = tid & 31;
        const int r0 = rg * 4;
        u64t acc[4][4]; float accs[4];
        #pragma unroll
        for (int j = 0; j < 4; j++) {
            float2 bv = __ldg((const float2*)(qkv_b + 2 * lane + 64 * j));
            u64t bj = pk2(bv.x, bv.y);
            #pragma unroll
            for (int r = 0; r < 4; r++) acc[r][j] = bj;
        }
        {
            float bs = __ldg(qkv_b + 256 + lane);
            #pragma unroll
            for (int r = 0; r < 4; r++) accs[r] = bs;
        }
        u64t wreg[3][4]; float wsreg[3];
        #pragma unroll
        for (int s = 0; s < 2; s++) {
            const float* wr = qkv_w + s * 288;
            #pragma unroll
            for (int j = 0; j < 4; j++) wreg[s][j] = ldg64(wr + 2 * lane + 64 * j);
            wsreg[s] = __ldg(wr + 256 + lane);
        }
        #pragma unroll 3
        for (int k = 0; k < C; k++) {
            const int sl = k % 3;
            const int kp = k + 2;
            if (kp < C) {
                const int sp2 = kp % 3;
                const float* wr = qkv_w + kp * 288;
                #pragma unroll
                for (int j = 0; j < 4; j++) wreg[sp2][j] = ldg64(wr + 2 * lane + 64 * j);
                wsreg[sp2] = __ldg(wr + 256 + lane);
            }
            u64t ad[4];
            #pragma unroll
            for (int r = 0; r < 4; r++) ad[r] = ldsb64(xdup + k * 130 + 2 * (r0 + r));
            #pragma unroll
            for (int j = 0; j < 4; j++) {
                #pragma unroll
                for (int r = 0; r < 4; r++) fma2(acc[r][j], ad[r], wreg[sl][j]);
            }
            #pragma unroll
            for (int r = 0; r < 4; r++) {
                float av = up2(ad[r]).x;
                accs[r] = fmaf(av, wsreg[sl], accs[r]);
            }
        }
        // scatter to qbuf / kT / vbuf
        #pragma unroll
        for (int r = 0; r < 4; r++) {
            int row = r0 + r;
            stsb64(qbuf + row * 100 + 2 * lane, acc[r][0]);
            {
                int c0 = 64 + 2 * lane;
                if (c0 < 96) {
                    stsb64(qbuf + row * 100 + c0, acc[r][1]);
                } else {
                    float2 t = up2(acc[r][1]);
                    int kc = c0 - 96;
                    kT[kc * 68 + row] = t.x;
                    kT[(kc + 1) * 68 + row] = t.y;
                }
            }
            {
                float2 t = up2(acc[r][2]);
                int kc = 32 + 2 * lane;
                kT[kc * 68 + row] = t.x;
                kT[(kc + 1) * 68 + row] = t.y;
            }
            stsb64(vbuf + row * 100 + 2 * lane, acc[r][3]);
            vbuf[row * 100 + 64 + lane] = accs[r];
        }
    }
    __syncthreads();

    float* oT = xdup;   // reuse

    // ---- attention (proven inner loops)
    {
        const int n = tid >> 3, sub = tid & 7;
        const int m0 = sub * 8;
        #pragma unroll 1
        for (int h = 0; h < NH; h++) {
            const int hb = h * HD;
            u64t qd[HD];
            #pragma unroll
            for (int dd = 0; dd < HD; dd++) qd[dd] = dup2(qbuf[n * 100 + hb + dd]);

            u64t p2[4] = {0ull, 0ull, 0ull, 0ull};
            #pragma unroll
            for (int dd = 0; dd < HD; dd++) {
                const float* kp = kT + (hb + dd) * 68 + m0;
                u64t k01, k23, k45, k67;
                ldsv2b64(k01, k23, kp);
                ldsv2b64(k45, k67, kp + 4);
                fma2(p2[0], qd[dd], k01); fma2(p2[1], qd[dd], k23);
                fma2(p2[2], qd[dd], k45); fma2(p2[3], qd[dd], k67);
            }
            float p[8];
            #pragma unroll
            for (int i = 0; i < 4; i++) { float2 t = up2(p2[i]); p[2*i] = t.x; p[2*i+1] = t.y; }
            #pragma unroll
            for (int i = 0; i < 8; i++) {
                int rdx = rel[n * 64 + m0 + i];
                p[i] = p[i] * 0.25f + sbias[rdx * NH + h];
            }
            float mx = -1e30f;
            #pragma unroll
            for (int i = 0; i < 8; i++) mx = fmaxf(mx, p[i]);
            mx = fmaxf(mx, __shfl_xor_sync(0xffffffffu, mx, 1));
            mx = fmaxf(mx, __shfl_xor_sync(0xffffffffu, mx, 2));
            mx = fmaxf(mx, __shfl_xor_sync(0xffffffffu, mx, 4));
            float sum = 0.f;
            #pragma unroll
            for (int i = 0; i < 8; i++) { p[i] = __expf(p[i] - mx); sum += p[i]; }
            sum += __shfl_xor_sync(0xffffffffu, sum, 1);
            sum += __shfl_xor_sync(0xffffffffu, sum, 2);
            sum += __shfl_xor_sync(0xffffffffu, sum, 4);
            float inv = 1.f / sum;
            #pragma unroll
            for (int i = 0; i < 8; i++) sbuf[n * 68 + m0 + i] = p[i] * inv;
            __syncwarp();

            float o0 = 0.f, o1 = 0.f, o0b = 0.f, o1b = 0.f;
            const float* vb = vbuf + hb + sub * 2;
            #pragma unroll
            for (int m4 = 0; m4 < 16; m4++) {
                float4 pr = ldsf4(sbuf + n * 68 + m4 * 4);
                const float* vm = vb + (m4 * 4) * 100;
                float2 v0 = ldsf2(vm);         o0  += pr.x * v0.x; o1  += pr.x * v0.y;
                float2 v1 = ldsf2(vm + 100);   o0b += pr.y * v1.x; o1b += pr.y * v1.y;
                float2 v2 = ldsf2(vm + 200);   o0  += pr.z * v2.x; o1  += pr.z * v2.y;
                float2 v3 = ldsf2(vm + 300);   o0b += pr.w * v3.x; o1b += pr.w * v3.y;
            }
            oT[(hb + sub * 2) * 68 + n]     = o0 + o0b;
            oT[(hb + sub * 2 + 1) * 68 + n] = o1 + o1b;
            __syncwarp();
        }
    }
    __syncthreads();

    // ---- proj [64x96]@[96x96], split-K 2, rolling prefetch + residual
    {
        const int kh = tid >> 8;
        const int t2 = tid & 255;
        const int rg = t2 >> 5, lane = t2 & 31;
        const int r0 = rg * 8;
        u64t acc[4][3];
        #pragma unroll
        for (int j = 0; j < 3; j++) {
            u64t bj = (kh == 0) ? dup2(__ldg(proj_b + lane + 32 * j)) : 0ull;
            #pragma unroll
            for (int p = 0; p < 4; p++) acc[p][j] = bj;
        }
        const int k0 = kh * 48;
        float wreg[3][3];
        #pragma unroll
        for (int s = 0; s < 2; s++) {
            const float* wr = proj_w + (k0 + s) * 96 + lane;
            #pragma unroll
            for (int j = 0; j < 3; j++) wreg[s][j] = __ldg(wr + 32 * j);
        }
        #pragma unroll 3
        for (int kk = 0; kk < 48; kk++) {
            const int sl = kk % 3;
            const int kp = kk + 2;
            if (kp < 48) {
                const float* wr = proj_w + (k0 + kp) * 96 + lane;
                #pragma unroll
                for (int j = 0; j < 3; j++) wreg[kp % 3][j] = __ldg(wr + 32 * j);
            }
            int k = k0 + kk;
            u64t a[4];
            ldsv2b64(a[0], a[1], oT + k * 68 + r0);
            ldsv2b64(a[2], a[3], oT + k * 68 + r0 + 4);
            #pragma unroll
            for (int j = 0; j < 3; j++) {
                u64t wd = dup2(wreg[sl][j]);
                #pragma unroll
                for (int p = 0; p < 4; p++) fma2(acc[p][j], a[p], wd);
            }
        }
        float* red = qbuf;   // [64][98]
        if (kh == 1) {
            #pragma unroll
            for (int p = 0; p < 4; p++) {
                int r = r0 + 2 * p;
                #pragma unroll
                for (int j = 0; j < 3; j++) {
                    int c = lane + 32 * j;
                    float2 t = up2(acc[p][j]);
                    red[r * 98 + c] = t.x;
                    red[(r + 1) * 98 + c] = t.y;
                }
            }
        }
        __syncthreads();
        if (kh == 0) {
            #pragma unroll
            for (int p = 0; p < 4; p++) {
                int r = r0 + 2 * p;
                size_t b0 = (size_t)(bb * LTOK + srcidx[r]) * C;
                size_t b1 = (size_t)(bb * LTOK + srcidx[r + 1]) * C;
                #pragma unroll
                for (int j = 0; j < 3; j++) {
                    int c = lane + 32 * j;
                    float2 t = up2(acc[p][j]);
                    g_ybuf[b0 + c] = x[b0 + c] + t.x + red[r * 98 + c];
                    g_ybuf[b1 + c] = x[b1 + c] + t.y + red[(r + 1) * 98 + c];
                }
            }
        }
    }
}

// ===========================================================================
// Kernel B: LN2 + MLP, rolling register prefetch of weights
// ===========================================================================
#define B_HID 0        // hidT [384][68]
#define B_H2D 26112    // h2dup [96][130]; reused as red [3][64][98]
#define B_TOT 44928

__global__ __launch_bounds__(512, 1)
void mlp_kernel(const float* __restrict__ g2, const float* __restrict__ b2,
                const float* __restrict__ w1, const float* __restrict__ bb1,
                const float* __restrict__ w2, const float* __restrict__ bb2,
                float* __restrict__ out)
{
    extern __shared__ float smf[];
    float* hidT  = smf + B_HID;
    float* h2dup = smf + B_H2D;

    const int tid = threadIdx.x;
    const int t0 = blockIdx.x * NW;

    // ---- LN2 -> h2dup[c][2n] dup pairs
    {
        const int n = tid >> 3, q8 = tid & 7;
        const float* yr = g_ybuf + (size_t)(t0 + n) * C + q8 * 12;
        float v[12]; float s = 0.f, ss = 0.f;
        #pragma unroll
        for (int j = 0; j < 12; j++) { float t = yr[j]; v[j] = t; s += t; ss += t * t; }
        s  += __shfl_xor_sync(0xffffffffu, s, 1);  ss += __shfl_xor_sync(0xffffffffu, ss, 1);
        s  += __shfl_xor_sync(0xffffffffu, s, 2);  ss += __shfl_xor_sync(0xffffffffu, ss, 2);
        s  += __shfl_xor_sync(0xffffffffu, s, 4);  ss += __shfl_xor_sync(0xffffffffu, ss, 4);
        float mean = s * (1.f / 96.f);
        float var  = ss * (1.f / 96.f) - mean * mean;
        float rstd = rsqrtf(var + 1e-5f);
        #pragma unroll
        for (int j = 0; j < 12; j++) {
            int c = q8 * 12 + j;
            float val = (v[j] - mean) * rstd * __ldg(g2 + c) + __ldg(b2 + c);
            stsb64(h2dup + c * 130 + 2 * n, dup2(val));
        }
    }
    __syncthreads();

    // ---- GEMM1 [64x96]@[96x384] + GELU -> hidT[c][n], rolling prefetch
    {
        const int rg = tid >> 5, lane = tid & 31;
        const int r0 = rg * 4;
        u64t acc[4][6];
        #pragma unroll
        for (int j = 0; j < 6; j++) {
            float2 bv = __ldg((const float2*)(bb1 + 2 * lane + 64 * j));
            u64t bj = pk2(bv.x, bv.y);
            #pragma unroll
            for (int r = 0; r < 4; r++) acc[r][j] = bj;
        }
        u64t wreg[3][6];
        #pragma unroll
        for (int s = 0; s < 2; s++) {
            const float* wr = w1 + s * MLPH;
            #pragma unroll
            for (int j = 0; j < 6; j++) wreg[s][j] = ldg64(wr + 2 * lane + 64 * j);
        }
        #pragma unroll 3
        for (int k = 0; k < C; k++) {
            const int sl = k % 3;
            const int kp = k + 2;
            if (kp < C) {
                const float* wr = w1 + kp * MLPH;
                #pragma unroll
                for (int j = 0; j < 6; j++)
                    wreg[kp % 3][j] = ldg64(wr + 2 * lane + 64 * j);
            }
            u64t ad[4];
            #pragma unroll
            for (int r = 0; r < 4; r++) ad[r] = ldsb64(h2dup + k * 130 + 2 * (r0 + r));
            #pragma unroll
            for (int j = 0; j < 6; j++) {
                #pragma unroll
                for (int r = 0; r < 4; r++) fma2(acc[r][j], ad[r], wreg[sl][j]);
            }
        }
        // GELU + store hidT
        #pragma unroll
        for (int r = 0; r < 4; r++) {
            int row = r0 + r;
            #pragma unroll
            for (int j = 0; j < 6; j++) {
                int cc = 2 * lane + 64 * j;
                float2 t = up2(acc[r][j]);
                float gx = 0.5f * t.x * (1.0f + erff(t.x * 0.70710678118654752f));
                float gy = 0.5f * t.y * (1.0f + erff(t.y * 0.70710678118654752f));
                hidT[cc * 68 + row] = gx;
                hidT[(cc + 1) * 68 + row] = gy;
            }
        }
    }
    __syncthreads();

    // ---- GEMM2 [64x384]@[384x96], split-K 4, rolling prefetch + residual
    {
        const int kh = tid >> 7;
        const int rg = (tid >> 5) & 3, lane = tid & 31;
        const int r0 = rg * 16;
        u64t acc[8][3];
        #pragma unroll
        for (int j = 0; j < 3; j++) {
            u64t bj = (kh == 0) ? dup2(__ldg(bb2 + lane + 32 * j)) : 0ull;
            #pragma unroll
            for (int p = 0; p < 8; p++) acc[p][j] = bj;
        }
        const int k0 = kh * 96;
        float wreg[3][3];
        #pragma unroll
        for (int s = 0; s < 2; s++) {
            const float* wr = w2 + (k0 + s) * 96 + lane;
            #pragma unroll
            for (int j = 0; j < 3; j++) wreg[s][j] = __ldg(wr + 32 * j);
        }
        #pragma unroll 3
        for (int kk = 0; kk < 96; kk++) {
            const int sl = kk % 3;
            const int kp = kk + 2;
            if (kp < 96) {
                const float* wr = w2 + (k0 + kp) * 96 + lane;
                #pragma unroll
                for (int j = 0; j < 3; j++) wreg[kp % 3][j] = __ldg(wr + 32 * j);
            }
            int k = k0 + kk;
            u64t a[8];
            const float* hp = hidT + k * 68 + r0;
            ldsv2b64(a[0], a[1], hp);
            ldsv2b64(a[2], a[3], hp + 4);
            ldsv2b64(a[4], a[5], hp + 8);
            ldsv2b64(a[6], a[7], hp + 12);
            #pragma unroll
            for (int j = 0; j < 3; j++) {
                u64t wd = dup2(wreg[sl][j]);
                #pragma unroll
                for (int p = 0; p < 8; p++) fma2(acc[p][j], a[p], wd);
            }
        }
        float* red = h2dup;   // [3][64][98]
        if (kh > 0) {
            float* rp = red + (kh - 1) * 6272;
            #pragma unroll
            for (int p = 0; p < 8; p++) {
                int r = r0 + 2 * p;
                #pragma unroll
                for (int j = 0; j < 3; j++) {
                    int c = lane + 32 * j;
                    float2 t = up2(acc[p][j]);
                    rp[r * 98 + c] = t.x;
                    rp[(r + 1) * 98 + c] = t.y;
                }
            }
        }
        __syncthreads();
        if (kh == 0) {
            #pragma unroll
            for (int p = 0; p < 8; p++) {
                int r = r0 + 2 * p;
                size_t b0 = (size_t)(t0 + r) * C;
                size_t b1 = (size_t)(t0 + r + 1) * C;
                #pragma unroll
                for (int j = 0; j < 3; j++) {
                    int c = lane + 32 * j;
                    float2 t = up2(acc[p][j]);
                    float s0 = t.x + red[r * 98 + c] + red[6272 + r * 98 + c]
                                   + red[12544 + r * 98 + c];
                    float s1 = t.y + red[(r + 1) * 98 + c] + red[6272 + (r + 1) * 98 + c]
                                   + red[12544 + (r + 1) * 98 + c];
                    out[b0 + c] = g_ybuf[b0 + c] + s0;
                    out[b1 + c] = g_ybuf[b1 + c] + s1;
                }
            }
        }
    }
}

// ---------------------------------------------------------------------------
extern "C" void kernel_launch(void* const* d_in, const int* in_sizes, int n_in,
                              void* d_out, int out_size)
{
    const float* x        = (const float*)d_in[0];
    const float* norm1_g  = (const float*)d_in[1];
    const float* norm1_b  = (const float*)d_in[2];
    const float* qkv_w    = (const float*)d_in[3];
    const float* qkv_b    = (const float*)d_in[4];
    const float* proj_w   = (const float*)d_in[5];
    const float* proj_b   = (const float*)d_in[6];
    const float* bias_tab = (const float*)d_in[7];
    const float* norm2_g  = (const float*)d_in[8];
    const float* norm2_b  = (const float*)d_in[9];
    const float* mlp_w1   = (const float*)d_in[10];
    const float* mlp_b1   = (const float*)d_in[11];
    const float* mlp_w2   = (const float*)d_in[12];
    const float* mlp_b2   = (const float*)d_in[13];
    float* out = (float*)d_out;

    cudaFuncSetAttribute(win_attn_kernel,
                         cudaFuncAttributeMaxDynamicSharedMemorySize, A_TOT * 4);
    cudaFuncSetAttribute(mlp_kernel,
                         cudaFuncAttributeMaxDynamicSharedMemorySize, B_TOT * 4);

    win_attn_kernel<<<NTILE, 512, A_TOT * 4>>>(x, norm1_g, norm1_b,
                                               qkv_w, qkv_b, proj_w, proj_b,
                                               bias_tab);
    mlp_kernel<<<NTILE, 512, B_TOT * 4>>>(norm2_g, norm2_b,
                                          mlp_w1, mlp_b1, mlp_w2, mlp_b2, out);
}

// round 10
// speedup vs baseline: 2.0382x; 2.0382x over previous
#include <cuda_runtime.h>
#include <math.h>

// ---------------------------------------------------------------------------
// SwinTransformerBlock3D — kernel A: fp32 f32x2 (R6, proven); kernel B: tf32 mma
// ---------------------------------------------------------------------------

#define LTOK (16*64*64)
#define BATCH 2
#define C 96
#define NH 6
#define HD 16
#define NW 64
#define MLPH 384
#define NTILE 2048

typedef unsigned long long u64t;

__device__ float g_ybuf[(size_t)BATCH * LTOK * C];

// ---------------- helpers --------------------------------------------------
__device__ __forceinline__ unsigned sp(const void* p) {
    return (unsigned)__cvta_generic_to_shared(p);
}
__device__ __forceinline__ u64t ldsb64(const float* p) {
    u64t v; asm volatile("ld.shared.b64 %0,[%1];" : "=l"(v) : "r"(sp(p))); return v;
}
__device__ __forceinline__ void ldsv2b64(u64t& a, u64t& b, const float* p) {
    asm volatile("ld.shared.v2.b64 {%0,%1},[%2];" : "=l"(a), "=l"(b) : "r"(sp(p)));
}
__device__ __forceinline__ float2 ldsf2(const float* p) {
    float2 r; asm volatile("ld.shared.v2.f32 {%0,%1},[%2];"
                           : "=f"(r.x), "=f"(r.y) : "r"(sp(p))); return r;
}
__device__ __forceinline__ float4 ldsf4(const float* p) {
    float4 r; asm volatile("ld.shared.v4.f32 {%0,%1,%2,%3},[%4];"
                           : "=f"(r.x),"=f"(r.y),"=f"(r.z),"=f"(r.w) : "r"(sp(p))); return r;
}
__device__ __forceinline__ unsigned ldsu32(const float* p) {
    unsigned v; asm volatile("ld.shared.b32 %0,[%1];" : "=r"(v) : "r"(sp(p))); return v;
}
__device__ __forceinline__ void stsb64(float* p, u64t v) {
    asm volatile("st.shared.b64 [%0],%1;" :: "r"(sp(p)), "l"(v));
}
__device__ __forceinline__ u64t pk2(float x, float y) {
    u64t r; asm("mov.b64 %0,{%1,%2};" : "=l"(r) : "f"(x), "f"(y)); return r;
}
__device__ __forceinline__ u64t dup2(float x) { return pk2(x, x); }
__device__ __forceinline__ float2 up2(u64t v) {
    float2 r; asm("mov.b64 {%0,%1},%2;" : "=f"(r.x), "=f"(r.y) : "l"(v)); return r;
}
__device__ __forceinline__ void fma2(u64t& d, u64t a, u64t b) {
    asm("fma.rn.f32x2 %0,%1,%2,%0;" : "+l"(d) : "l"(a), "l"(b));
}
__device__ __forceinline__ u64t ldg64(const float* p) {
    return __ldg((const u64t*)p);
}
__device__ __forceinline__ float tf32f(float x) {
    unsigned r; asm("cvt.rna.tf32.f32 %0,%1;" : "=r"(r) : "f"(x));
    return __uint_as_float(r);
}
__device__ __forceinline__ void mma8(float* d, const unsigned* a,
                                     unsigned b0, unsigned b1) {
    asm("mma.sync.aligned.m16n8k8.row.col.f32.tf32.tf32.f32 "
        "{%0,%1,%2,%3},{%4,%5,%6,%7},{%8,%9},{%0,%1,%2,%3};"
        : "+f"(d[0]), "+f"(d[1]), "+f"(d[2]), "+f"(d[3])
        : "r"(a[0]), "r"(a[1]), "r"(a[2]), "r"(a[3]), "r"(b0), "r"(b1));
}

// ======================= Kernel A (R6, unchanged) ==========================
#define A_XD   0
#define A_Q    12480
#define A_KT   18880
#define A_V    25408
#define A_S    31808
#define A_BIAS 36160
#define A_REL  38218
#define A_SRC  40266
#define A_TOT  40330

__global__ __launch_bounds__(512, 1)
void win_attn_kernel(const float* __restrict__ x,
                     const float* __restrict__ g1, const float* __restrict__ b1,
                     const float* __restrict__ qkv_w, const float* __restrict__ qkv_b,
                     const float* __restrict__ proj_w, const float* __restrict__ proj_b,
                     const float* __restrict__ bias_table)
{
    extern __shared__ float smf[];
    float* xdup = smf + A_XD;
    float* qbuf = smf + A_Q;
    float* kT   = smf + A_KT;
    float* vbuf = smf + A_V;
    float* sbuf = smf + A_S;
    float* sbias = smf + A_BIAS;
    unsigned short* rel = (unsigned short*)(smf + A_REL);
    int* srcidx = (int*)(smf + A_SRC);

    const int tid = threadIdx.x;
    const int wb = blockIdx.x;
    const int bb = wb >> 10;
    const int w  = wb & 1023;
    const int iw = w >> 8, xw = (w >> 4) & 15, tw = w & 15;

    if (tid < NW) {
        int i = tid >> 4, xx = (tid >> 2) & 3, tt = tid & 3;
        int gi = (iw * 4 + i  + 2) & 15;
        int gx = (xw * 4 + xx + 2) & 63;
        int gt = (tw * 4 + tt + 2) & 63;
        srcidx[tid] = ((gi << 6) + gx) * 64 + gt;
    }
    for (int p = tid; p < 4096; p += 512) {
        int n = p >> 6, m = p & 63;
        int di = (n >> 4)       - (m >> 4)       + 3;
        int dx = ((n >> 2) & 3) - ((m >> 2) & 3) + 3;
        int dt = (n & 3)        - (m & 3)        + 3;
        rel[p] = (unsigned short)((di * 7 + dx) * 7 + dt);
    }
    for (int i = tid; i < 343 * NH; i += 512) sbias[i] = __ldg(bias_table + i);
    __syncthreads();

    // ---- LN1 -> xdup[c][2n] dup pairs
    {
        const int n = tid >> 3, q8 = tid & 7;
        const float* xr = x + ((size_t)(bb * LTOK + srcidx[n])) * C + q8 * 12;
        float v[12]; float s = 0.f, ss = 0.f;
        #pragma unroll
        for (int j = 0; j < 12; j++) { float t = xr[j]; v[j] = t; s += t; ss += t * t; }
        s  += __shfl_xor_sync(0xffffffffu, s, 1);  ss += __shfl_xor_sync(0xffffffffu, ss, 1);
        s  += __shfl_xor_sync(0xffffffffu, s, 2);  ss += __shfl_xor_sync(0xffffffffu, ss, 2);
        s  += __shfl_xor_sync(0xffffffffu, s, 4);  ss += __shfl_xor_sync(0xffffffffu, ss, 4);
        float mean = s * (1.f / 96.f);
        float var  = ss * (1.f / 96.f) - mean * mean;
        float rstd = rsqrtf(var + 1e-5f);
        #pragma unroll
        for (int j = 0; j < 12; j++) {
            int c = q8 * 12 + j;
            float val = (v[j] - mean) * rstd * __ldg(g1 + c) + __ldg(b1 + c);
            stsb64(xdup + c * 130 + 2 * n, dup2(val));
        }
    }
    __syncthreads();

    // ---- QKV GEMM [64x96]@[96x288]
    {
        const int rg = tid >> 5, lane = tid & 31;
        const int r0 = rg * 4;
        u64t acc[4][4]; float accs[4];
        #pragma unroll
        for (int j = 0; j < 4; j++) {
            float2 bv = __ldg((const float2*)(qkv_b + 2 * lane + 64 * j));
            u64t bj = pk2(bv.x, bv.y);
            #pragma unroll
            for (int r = 0; r < 4; r++) acc[r][j] = bj;
        }
        {
            float bs = __ldg(qkv_b + 256 + lane);
            #pragma unroll
            for (int r = 0; r < 4; r++) accs[r] = bs;
        }
        #pragma unroll 2
        for (int k = 0; k < C; k++) {
            u64t ad[4];
            #pragma unroll
            for (int r = 0; r < 4; r++) ad[r] = ldsb64(xdup + k * 130 + 2 * (r0 + r));
            const float* wr = qkv_w + k * 288;
            #pragma unroll
            for (int j = 0; j < 4; j++) {
                u64t wp = ldg64(wr + 2 * lane + 64 * j);
                #pragma unroll
                for (int r = 0; r < 4; r++) fma2(acc[r][j], ad[r], wp);
            }
            float wsc = __ldg(wr + 256 + lane);
            #pragma unroll
            for (int r = 0; r < 4; r++) {
                float av = up2(ad[r]).x;
                accs[r] = fmaf(av, wsc, accs[r]);
            }
        }
        #pragma unroll
        for (int r = 0; r < 4; r++) {
            int row = r0 + r;
            stsb64(qbuf + row * 100 + 2 * lane, acc[r][0]);
            {
                int c0 = 64 + 2 * lane;
                if (c0 < 96) {
                    stsb64(qbuf + row * 100 + c0, acc[r][1]);
                } else {
                    float2 t = up2(acc[r][1]);
                    int kc = c0 - 96;
                    kT[kc * 68 + row] = t.x;
                    kT[(kc + 1) * 68 + row] = t.y;
                }
            }
            {
                float2 t = up2(acc[r][2]);
                int kc = 32 + 2 * lane;
                kT[kc * 68 + row] = t.x;
                kT[(kc + 1) * 68 + row] = t.y;
            }
            stsb64(vbuf + row * 100 + 2 * lane, acc[r][3]);
            vbuf[row * 100 + 64 + lane] = accs[r];
        }
    }
    __syncthreads();

    float* oT = xdup;

    // ---- attention
    {
        const int n = tid >> 3, sub = tid & 7;
        const int m0 = sub * 8;
        #pragma unroll 1
        for (int h = 0; h < NH; h++) {
            const int hb = h * HD;
            u64t qd[HD];
            #pragma unroll
            for (int dd = 0; dd < HD; dd++) qd[dd] = dup2(qbuf[n * 100 + hb + dd]);

            u64t p2[4] = {0ull, 0ull, 0ull, 0ull};
            #pragma unroll
            for (int dd = 0; dd < HD; dd++) {
                const float* kp = kT + (hb + dd) * 68 + m0;
                u64t k01, k23, k45, k67;
                ldsv2b64(k01, k23, kp);
                ldsv2b64(k45, k67, kp + 4);
                fma2(p2[0], qd[dd], k01); fma2(p2[1], qd[dd], k23);
                fma2(p2[2], qd[dd], k45); fma2(p2[3], qd[dd], k67);
            }
            float p[8];
            #pragma unroll
            for (int i = 0; i < 4; i++) { float2 t = up2(p2[i]); p[2*i] = t.x; p[2*i+1] = t.y; }
            #pragma unroll
            for (int i = 0; i < 8; i++) {
                int rdx = rel[n * 64 + m0 + i];
                p[i] = p[i] * 0.25f + sbias[rdx * NH + h];
            }
            float mx = -1e30f;
            #pragma unroll
            for (int i = 0; i < 8; i++) mx = fmaxf(mx, p[i]);
            mx = fmaxf(mx, __shfl_xor_sync(0xffffffffu, mx, 1));
            mx = fmaxf(mx, __shfl_xor_sync(0xffffffffu, mx, 2));
            mx = fmaxf(mx, __shfl_xor_sync(0xffffffffu, mx, 4));
            float sum = 0.f;
            #pragma unroll
            for (int i = 0; i < 8; i++) { p[i] = __expf(p[i] - mx); sum += p[i]; }
            sum += __shfl_xor_sync(0xffffffffu, sum, 1);
            sum += __shfl_xor_sync(0xffffffffu, sum, 2);
            sum += __shfl_xor_sync(0xffffffffu, sum, 4);
            float inv = 1.f / sum;
            #pragma unroll
            for (int i = 0; i < 8; i++) sbuf[n * 68 + m0 + i] = p[i] * inv;
            __syncwarp();

            float o0 = 0.f, o1 = 0.f, o0b = 0.f, o1b = 0.f;
            const float* vb = vbuf + hb + sub * 2;
            #pragma unroll
            for (int m4 = 0; m4 < 16; m4++) {
                float4 pr = ldsf4(sbuf + n * 68 + m4 * 4);
                const float* vm = vb + (m4 * 4) * 100;
                float2 v0 = ldsf2(vm);         o0  += pr.x * v0.x; o1  += pr.x * v0.y;
                float2 v1 = ldsf2(vm + 100);   o0b += pr.y * v1.x; o1b += pr.y * v1.y;
                float2 v2 = ldsf2(vm + 200);   o0  += pr.z * v2.x; o1  += pr.z * v2.y;
                float2 v3 = ldsf2(vm + 300);   o0b += pr.w * v3.x; o1b += pr.w * v3.y;
            }
            oT[(hb + sub * 2) * 68 + n]     = o0 + o0b;
            oT[(hb + sub * 2 + 1) * 68 + n] = o1 + o1b;
            __syncwarp();
        }
    }
    __syncthreads();

    // ---- proj + residual
    {
        const int kh = tid >> 8;
        const int t2 = tid & 255;
        const int rg = t2 >> 5, lane = t2 & 31;
        const int r0 = rg * 8;
        u64t acc[4][3];
        #pragma unroll
        for (int j = 0; j < 3; j++) {
            u64t bj = (kh == 0) ? dup2(__ldg(proj_b + lane + 32 * j)) : 0ull;
            #pragma unroll
            for (int p = 0; p < 4; p++) acc[p][j] = bj;
        }
        const int k0 = kh * 48;
        #pragma unroll 2
        for (int kk = 0; kk < 48; kk++) {
            int k = k0 + kk;
            u64t a[4];
            ldsv2b64(a[0], a[1], oT + k * 68 + r0);
            ldsv2b64(a[2], a[3], oT + k * 68 + r0 + 4);
            const float* wr = proj_w + k * 96 + lane;
            #pragma unroll
            for (int j = 0; j < 3; j++) {
                u64t wd = dup2(__ldg(wr + 32 * j));
                #pragma unroll
                for (int p = 0; p < 4; p++) fma2(acc[p][j], a[p], wd);
            }
        }
        float* red = qbuf;
        if (kh == 1) {
            #pragma unroll
            for (int p = 0; p < 4; p++) {
                int r = r0 + 2 * p;
                #pragma unroll
                for (int j = 0; j < 3; j++) {
                    int c = lane + 32 * j;
                    float2 t = up2(acc[p][j]);
                    red[r * 98 + c] = t.x;
                    red[(r + 1) * 98 + c] = t.y;
                }
            }
        }
        __syncthreads();
        if (kh == 0) {
            #pragma unroll
            for (int p = 0; p < 4; p++) {
                int r = r0 + 2 * p;
                size_t b0 = (size_t)(bb * LTOK + srcidx[r]) * C;
                size_t b1 = (size_t)(bb * LTOK + srcidx[r + 1]) * C;
                #pragma unroll
                for (int j = 0; j < 3; j++) {
                    int c = lane + 32 * j;
                    float2 t = up2(acc[p][j]);
                    g_ybuf[b0 + c] = x[b0 + c] + t.x + red[r * 98 + c];
                    g_ybuf[b1 + c] = x[b1 + c] + t.y + red[(r + 1) * 98 + c];
                }
            }
        }
    }
}

// ======================= Kernel B: tf32 mma MLP ============================
#define SM_HID 0        // hid [64][392]                      (25088)
#define SM_H2S 25088    // h2s [64][104]                      (6656)
#define SM_W1C 31744    // w1 chunk [32][396]                 (12672)
#define SM_W2C 25088    // w2 chunk [64][396] (reuses h2s+w1c region, 25344)
#define B_TOT  50432

__global__ __launch_bounds__(512, 1)
void mlp_kernel(const float* __restrict__ g2, const float* __restrict__ b2,
                const float* __restrict__ w1, const float* __restrict__ bb1,
                const float* __restrict__ w2, const float* __restrict__ bb2,
                float* __restrict__ out)
{
    extern __shared__ float smf[];
    float* hid = smf + SM_HID;
    float* h2s = smf + SM_H2S;
    float* w1c = smf + SM_W1C;
    float* w2c = smf + SM_W2C;

    const int tid = threadIdx.x;
    const int t0 = blockIdx.x * NW;
    const int lane = tid & 31, wid = tid >> 5;
    const int g = lane >> 2, cq = lane & 3;

    // prefetch w1 chunk 0 (32x384 = 12288 floats; 24/thread, row-aligned)
    float4 wpf[6];
    {
        const float* src = w1 + tid * 24;
        #pragma unroll
        for (int i = 0; i < 6; i++) wpf[i] = __ldg((const float4*)(src + 4 * i));
    }

    // ---- LN2 -> h2s[n][104] (tf32-rounded)
    {
        const int n = tid >> 3, q8 = tid & 7;
        const float* yr = g_ybuf + (size_t)(t0 + n) * C + q8 * 12;
        float v[12]; float s = 0.f, ss = 0.f;
        #pragma unroll
        for (int j = 0; j < 12; j++) { float t = yr[j]; v[j] = t; s += t; ss += t * t; }
        s  += __shfl_xor_sync(0xffffffffu, s, 1);  ss += __shfl_xor_sync(0xffffffffu, ss, 1);
        s  += __shfl_xor_sync(0xffffffffu, s, 2);  ss += __shfl_xor_sync(0xffffffffu, ss, 2);
        s  += __shfl_xor_sync(0xffffffffu, s, 4);  ss += __shfl_xor_sync(0xffffffffu, ss, 4);
        float mean = s * (1.f / 96.f);
        float var  = ss * (1.f / 96.f) - mean * mean;
        float rstd = rsqrtf(var + 1e-5f);
        #pragma unroll
        for (int j = 0; j < 12; j++) {
            int c = q8 * 12 + j;
            float val = (v[j] - mean) * rstd * __ldg(g2 + c) + __ldg(b2 + c);
            h2s[n * 104 + c] = tf32f(val);
        }
    }

    // ---- GEMM1 (m16n8k8): warp = 2 m-tiles x 6 n-tiles
    const int mh = wid & 1, ng = wid >> 1;
    const int m0 = 32 * mh, n0 = 48 * ng;
    float acc1[2][6][4];
    #pragma unroll
    for (int nt = 0; nt < 6; nt++) {
        int col = n0 + 8 * nt + 2 * cq;
        float bx = __ldg(bb1 + col), by = __ldg(bb1 + col + 1);
        #pragma unroll
        for (int mi = 0; mi < 2; mi++) {
            acc1[mi][nt][0] = bx; acc1[mi][nt][1] = by;
            acc1[mi][nt][2] = bx; acc1[mi][nt][3] = by;
        }
    }
    {   // stage chunk 0
        int kk = (tid * 24) / 384, nn = (tid * 24) % 384;
        float* d = w1c + kk * 396 + nn;
        const float* pv = (const float*)wpf;
        #pragma unroll
        for (int i = 0; i < 24; i++) d[i] = tf32f(pv[i]);
    }
    __syncthreads();

    #pragma unroll 1
    for (int c3 = 0; c3 < 3; c3++) {
        if (c3 < 2) {
            const float* src = w1 + (c3 + 1) * 12288 + tid * 24;
            #pragma unroll
            for (int i = 0; i < 6; i++) wpf[i] = __ldg((const float4*)(src + 4 * i));
        }
        #pragma unroll
        for (int kq = 0; kq < 4; kq++) {
            const int kb = 8 * kq;
            const int kA = 32 * c3 + kb + 2 * cq;
            unsigned A[2][4];
            #pragma unroll
            for (int mi = 0; mi < 2; mi++) {
                int row = m0 + 16 * mi + g;
                u64t lo = ldsb64(h2s + row * 104 + kA);
                u64t hi = ldsb64(h2s + (row + 8) * 104 + kA);
                A[mi][0] = (unsigned)lo; A[mi][2] = (unsigned)(lo >> 32);
                A[mi][1] = (unsigned)hi; A[mi][3] = (unsigned)(hi >> 32);
            }
            #pragma unroll
            for (int nt = 0; nt < 6; nt++) {
                const float* wp = w1c + (kb + 2 * cq) * 396 + n0 + 8 * nt + g;
                unsigned b0 = ldsu32(wp);
                unsigned b1 = ldsu32(wp + 396);
                mma8(acc1[0][nt], A[0], b0, b1);
                mma8(acc1[1][nt], A[1], b0, b1);
            }
        }
        __syncthreads();
        if (c3 < 2) {
            int kk = (tid * 24) / 384, nn = (tid * 24) % 384;
            float* d = w1c + kk * 396 + nn;
            const float* pv = (const float*)wpf;
            #pragma unroll
            for (int i = 0; i < 24; i++) d[i] = tf32f(pv[i]);
            __syncthreads();
        }
    }

    // GELU + tf32 round -> hid[64][392]
    #pragma unroll
    for (int mi = 0; mi < 2; mi++) {
        #pragma unroll
        for (int nt = 0; nt < 6; nt++) {
            int row = m0 + 16 * mi + g;
            int col = n0 + 8 * nt + 2 * cq;
            float* a = acc1[mi][nt];
            float g0 = 0.5f * a[0] * (1.0f + erff(a[0] * 0.70710678118654752f));
            float g1 = 0.5f * a[1] * (1.0f + erff(a[1] * 0.70710678118654752f));
            float g2v = 0.5f * a[2] * (1.0f + erff(a[2] * 0.70710678118654752f));
            float g3 = 0.5f * a[3] * (1.0f + erff(a[3] * 0.70710678118654752f));
            stsb64(hid + row * 392 + col, pk2(tf32f(g0), tf32f(g1)));
            stsb64(hid + (row + 8) * 392 + col, pk2(tf32f(g2v), tf32f(g3)));
        }
    }

    // ---- GEMM2 (m16n8k8): warp = 1 m-tile x 3 n-tiles
    // 6 chunks of 64 k-rows; chunk = 64*96 = 6144 floats = 12/thread (3 float4)
    const int mt = wid & 3, n3 = wid >> 2;
    const int m0b = 16 * mt, n0b = 24 * n3;
    float acc2[3][4];
    #pragma unroll
    for (int nt = 0; nt < 3; nt++) {
        int col = n0b + 8 * nt + 2 * cq;
        float bx = __ldg(bb2 + col), by = __ldg(bb2 + col + 1);
        acc2[nt][0] = bx; acc2[nt][1] = by;
        acc2[nt][2] = bx; acc2[nt][3] = by;
    }
    float4 wpf2[3];
    {
        const float* src = w2 + tid * 12;
        #pragma unroll
        for (int i = 0; i < 3; i++) wpf2[i] = __ldg((const float4*)(src + 4 * i));
    }
    __syncthreads();   // all warps done reading w1c/h2s; hid fully written

    #pragma unroll 1
    for (int ch = 0; ch < 6; ch++) {
        {   // stage chunk ch (tf32-rounded); tid*12 stays within one 96-col row
            int base = tid * 12;
            int kk = base / 96, nn = base % 96;
            float* d = w2c + kk * 396 + nn;
            const float* pv = (const float*)wpf2;
            #pragma unroll
            for (int i = 0; i < 12; i++) d[i] = tf32f(pv[i]);
        }
        __syncthreads();
        if (ch < 5) {
            const float* src = w2 + (ch + 1) * 6144 + tid * 12;
            #pragma unroll
            for (int i = 0; i < 3; i++) wpf2[i] = __ldg((const float4*)(src + 4 * i));
        }
        #pragma unroll
        for (int kq = 0; kq < 8; kq++) {
            const int kb = 8 * kq;
            const int kA = 64 * ch + kb + 2 * cq;
            unsigned A[4];
            u64t lo = ldsb64(hid + (m0b + g) * 392 + kA);
            u64t hi = ldsb64(hid + (m0b + g + 8) * 392 + kA);
            A[0] = (unsigned)lo; A[2] = (unsigned)(lo >> 32);
            A[1] = (unsigned)hi; A[3] = (unsigned)(hi >> 32);
            #pragma unroll
            for (int nt = 0; nt < 3; nt++) {
                const float* wp = w2c + (kb + 2 * cq) * 396 + n0b + 8 * nt + g;
                unsigned b0 = ldsu32(wp);
                unsigned b1 = ldsu32(wp + 396);
                mma8(acc2[nt], A, b0, b1);
            }
        }
        __syncthreads();
    }

    // epilogue: residual + store
    #pragma unroll
    for (int nt = 0; nt < 3; nt++) {
        int col = n0b + 8 * nt + 2 * cq;
        int r0 = t0 + m0b + g;
        const float2 y0 = *(const float2*)(g_ybuf + (size_t)r0 * C + col);
        const float2 y1 = *(const float2*)(g_ybuf + (size_t)(r0 + 8) * C + col);
        float2 o0 = make_float2(y0.x + acc2[nt][0], y0.y + acc2[nt][1]);
        float2 o1 = make_float2(y1.x + acc2[nt][2], y1.y + acc2[nt][3]);
        *(float2*)(out + (size_t)r0 * C + col) = o0;
        *(float2*)(out + (size_t)(r0 + 8) * C + col) = o1;
    }
}

// ---------------------------------------------------------------------------
extern "C" void kernel_launch(void* const* d_in, const int* in_sizes, int n_in,
                              void* d_out, int out_size)
{
    const float* x        = (const float*)d_in[0];
    const float* norm1_g  = (const float*)d_in[1];
    const float* norm1_b  = (const float*)d_in[2];
    const float* qkv_w    = (const float*)d_in[3];
    const float* qkv_b    = (const float*)d_in[4];
    const float* proj_w   = (const float*)d_in[5];
    const float* proj_b   = (const float*)d_in[6];
    const float* bias_tab = (const float*)d_in[7];
    const float* norm2_g  = (const float*)d_in[8];
    const float* norm2_b  = (const float*)d_in[9];
    const float* mlp_w1   = (const float*)d_in[10];
    const float* mlp_b1   = (const float*)d_in[11];
    const float* mlp_w2   = (const float*)d_in[12];
    const float* mlp_b2   = (const float*)d_in[13];
    float* out = (float*)d_out;

    cudaFuncSetAttribute(win_attn_kernel,
                         cudaFuncAttributeMaxDynamicSharedMemorySize, A_TOT * 4);
    cudaFuncSetAttribute(mlp_kernel,
                         cudaFuncAttributeMaxDynamicSharedMemorySize, B_TOT * 4);

    win_attn_kernel<<<NTILE, 512, A_TOT * 4>>>(x, norm1_g, norm1_b,
                                               qkv_w, qkv_b, proj_w, proj_b,
                                               bias_tab);
    mlp_kernel<<<NTILE, 512, B_TOT * 4>>>(norm2_g, norm2_b,
                                          mlp_w1, mlp_b1, mlp_w2, mlp_b2, out);
}

// round 11
// speedup vs baseline: 2.5491x; 1.2507x over previous
#include <cuda_runtime.h>
#include <math.h>

// ---------------------------------------------------------------------------
// SwinTransformerBlock3D — tf32 m16n8k8 for all four GEMMs; scalar attention
// ---------------------------------------------------------------------------

#define LTOK (16*64*64)
#define BATCH 2
#define C 96
#define NH 6
#define HD 16
#define NW 64
#define MLPH 384
#define NTILE 2048

typedef unsigned long long u64t;

__device__ float g_ybuf[(size_t)BATCH * LTOK * C];

// ---------------- helpers --------------------------------------------------
__device__ __forceinline__ unsigned sp(const void* p) {
    return (unsigned)__cvta_generic_to_shared(p);
}
__device__ __forceinline__ u64t ldsb64(const float* p) {
    u64t v; asm volatile("ld.shared.b64 %0,[%1];" : "=l"(v) : "r"(sp(p))); return v;
}
__device__ __forceinline__ void ldsv2b64(u64t& a, u64t& b, const float* p) {
    asm volatile("ld.shared.v2.b64 {%0,%1},[%2];" : "=l"(a), "=l"(b) : "r"(sp(p)));
}
__device__ __forceinline__ float2 ldsf2(const float* p) {
    float2 r; asm volatile("ld.shared.v2.f32 {%0,%1},[%2];"
                           : "=f"(r.x), "=f"(r.y) : "r"(sp(p))); return r;
}
__device__ __forceinline__ float4 ldsf4(const float* p) {
    float4 r; asm volatile("ld.shared.v4.f32 {%0,%1,%2,%3},[%4];"
                           : "=f"(r.x),"=f"(r.y),"=f"(r.z),"=f"(r.w) : "r"(sp(p))); return r;
}
__device__ __forceinline__ unsigned ldsu32(const float* p) {
    unsigned v; asm volatile("ld.shared.b32 %0,[%1];" : "=r"(v) : "r"(sp(p))); return v;
}
__device__ __forceinline__ void stsb64(float* p, u64t v) {
    asm volatile("st.shared.b64 [%0],%1;" :: "r"(sp(p)), "l"(v));
}
__device__ __forceinline__ u64t pk2(float x, float y) {
    u64t r; asm("mov.b64 %0,{%1,%2};" : "=l"(r) : "f"(x), "f"(y)); return r;
}
__device__ __forceinline__ u64t dup2(float x) { return pk2(x, x); }
__device__ __forceinline__ float2 up2(u64t v) {
    float2 r; asm("mov.b64 {%0,%1},%2;" : "=f"(r.x), "=f"(r.y) : "l"(v)); return r;
}
__device__ __forceinline__ void fma2(u64t& d, u64t a, u64t b) {
    asm("fma.rn.f32x2 %0,%1,%2,%0;" : "+l"(d) : "l"(a), "l"(b));
}
__device__ __forceinline__ float tf32f(float x) {
    unsigned r; asm("cvt.rna.tf32.f32 %0,%1;" : "=r"(r) : "f"(x));
    return __uint_as_float(r);
}
__device__ __forceinline__ void mma8(float* d, const unsigned* a,
                                     unsigned b0, unsigned b1) {
    asm("mma.sync.aligned.m16n8k8.row.col.f32.tf32.tf32.f32 "
        "{%0,%1,%2,%3},{%4,%5,%6,%7},{%8,%9},{%0,%1,%2,%3};"
        : "+f"(d[0]), "+f"(d[1]), "+f"(d[2]), "+f"(d[3])
        : "r"(a[0]), "r"(a[1]), "r"(a[2]), "r"(a[3]), "r"(b0), "r"(b1));
}

// ======================= Kernel A: tf32 QKV/proj + scalar attention ========
#define A_XS   0        // xs [64][104] tf32 LN1; reused as obuf [64][104]
#define A_Q    6656     // qbuf [64][100]
#define A_KT   13056    // kT [96][68]
#define A_V    19584    // vbuf [64][100]
#define A_S    25984    // sbuf [64][68]
#define A_WC   30336    // qkv chunk [32][292] (9344) / proj_w [96][100] (9600)
#define A_BIAS 39936    // 2058
#define A_REL  41994    // u16[4096] = 2048 floats
#define A_SRC  44042    // int[64]
#define A_TOT  44106

__global__ __launch_bounds__(512, 1)
void win_attn_kernel(const float* __restrict__ x,
                     const float* __restrict__ g1, const float* __restrict__ b1,
                     const float* __restrict__ qkv_w, const float* __restrict__ qkv_b,
                     const float* __restrict__ proj_w, const float* __restrict__ proj_b,
                     const float* __restrict__ bias_table)
{
    extern __shared__ float smf[];
    float* xs   = smf + A_XS;
    float* qbuf = smf + A_Q;
    float* kT   = smf + A_KT;
    float* vbuf = smf + A_V;
    float* sbuf = smf + A_S;
    float* wc   = smf + A_WC;
    float* sbias = smf + A_BIAS;
    unsigned short* rel = (unsigned short*)(smf + A_REL);
    int* srcidx = (int*)(smf + A_SRC);

    const int tid = threadIdx.x;
    const int lane = tid & 31, wid = tid >> 5;
    const int g = lane >> 2, cq = lane & 3;
    const int wb = blockIdx.x;
    const int bb = wb >> 10;
    const int w  = wb & 1023;
    const int iw = w >> 8, xw = (w >> 4) & 15, tw = w & 15;

    // prefetch qkv_w chunk 0 (32x288 = 9216 floats; 18/thread, row-aligned)
    float2 wpf[9];
    {
        const float* src = qkv_w + tid * 18;
        #pragma unroll
        for (int i = 0; i < 9; i++) wpf[i] = __ldg((const float2*)(src + 2 * i));
    }

    if (tid < NW) {
        int i = tid >> 4, xx = (tid >> 2) & 3, tt = tid & 3;
        int gi = (iw * 4 + i  + 2) & 15;
        int gx = (xw * 4 + xx + 2) & 63;
        int gt = (tw * 4 + tt + 2) & 63;
        srcidx[tid] = ((gi << 6) + gx) * 64 + gt;
    }
    for (int p = tid; p < 4096; p += 512) {
        int n = p >> 6, m = p & 63;
        int di = (n >> 4)       - (m >> 4)       + 3;
        int dx = ((n >> 2) & 3) - ((m >> 2) & 3) + 3;
        int dt = (n & 3)        - (m & 3)        + 3;
        rel[p] = (unsigned short)((di * 7 + dx) * 7 + dt);
    }
    for (int i = tid; i < 343 * NH; i += 512) sbias[i] = __ldg(bias_table + i);
    __syncthreads();

    // ---- LN1 -> xs[n][104] (tf32-rounded)
    {
        const int n = tid >> 3, q8 = tid & 7;
        const float* xr = x + ((size_t)(bb * LTOK + srcidx[n])) * C + q8 * 12;
        float v[12]; float s = 0.f, ss = 0.f;
        #pragma unroll
        for (int j = 0; j < 12; j++) { float t = xr[j]; v[j] = t; s += t; ss += t * t; }
        s  += __shfl_xor_sync(0xffffffffu, s, 1);  ss += __shfl_xor_sync(0xffffffffu, ss, 1);
        s  += __shfl_xor_sync(0xffffffffu, s, 2);  ss += __shfl_xor_sync(0xffffffffu, ss, 2);
        s  += __shfl_xor_sync(0xffffffffu, s, 4);  ss += __shfl_xor_sync(0xffffffffu, ss, 4);
        float mean = s * (1.f / 96.f);
        float var  = ss * (1.f / 96.f) - mean * mean;
        float rstd = rsqrtf(var + 1e-5f);
        #pragma unroll
        for (int j = 0; j < 12; j++) {
            int c = q8 * 12 + j;
            float val = (v[j] - mean) * rstd * __ldg(g1 + c) + __ldg(b1 + c);
            xs[n * 104 + c] = tf32f(val);
        }
    }

    // ---- QKV GEMM (m16n8k8): warp = 1 m-tile x 9 n-tiles (72 cols)
    {
        const int mt = wid & 3, ng = wid >> 2;
        const int m0 = 16 * mt, n0 = 72 * ng;
        float acc[9][4];
        #pragma unroll
        for (int nt = 0; nt < 9; nt++) {
            int col = n0 + 8 * nt + 2 * cq;
            float bx = __ldg(qkv_b + col), by = __ldg(qkv_b + col + 1);
            acc[nt][0] = bx; acc[nt][1] = by;
            acc[nt][2] = bx; acc[nt][3] = by;
        }
        {   // stage chunk 0
            int kk = tid >> 4, nn = (tid & 15) * 18;
            float* d = wc + kk * 292 + nn;
            const float* pv = (const float*)wpf;
            #pragma unroll
            for (int i = 0; i < 18; i++) d[i] = tf32f(pv[i]);
        }
        __syncthreads();

        #pragma unroll 1
        for (int c3 = 0; c3 < 3; c3++) {
            if (c3 < 2) {
                const float* src = qkv_w + (c3 + 1) * 9216 + tid * 18;
                #pragma unroll
                for (int i = 0; i < 9; i++) wpf[i] = __ldg((const float2*)(src + 2 * i));
            }
            #pragma unroll
            for (int kq = 0; kq < 4; kq++) {
                const int kloc = 8 * kq + 2 * cq;
                const int kA = 32 * c3 + kloc;
                unsigned A[4];
                u64t lo = ldsb64(xs + (m0 + g) * 104 + kA);
                u64t hi = ldsb64(xs + (m0 + g + 8) * 104 + kA);
                A[0] = (unsigned)lo; A[2] = (unsigned)(lo >> 32);
                A[1] = (unsigned)hi; A[3] = (unsigned)(hi >> 32);
                #pragma unroll
                for (int nt = 0; nt < 9; nt++) {
                    const float* wp = wc + kloc * 292 + n0 + 8 * nt + g;
                    unsigned b0 = ldsu32(wp);
                    unsigned b1 = ldsu32(wp + 292);
                    mma8(acc[nt], A, b0, b1);
                }
            }
            __syncthreads();
            if (c3 < 2) {
                int kk = tid >> 4, nn = (tid & 15) * 18;
                float* d = wc + kk * 292 + nn;
                const float* pv = (const float*)wpf;
                #pragma unroll
                for (int i = 0; i < 18; i++) d[i] = tf32f(pv[i]);
                __syncthreads();
            }
        }

        // scatter fragments to qbuf / kT / vbuf
        #pragma unroll
        for (int nt = 0; nt < 9; nt++) {
            int col = n0 + 8 * nt + 2 * cq;
            int r = m0 + g;
            if (col < 96) {
                stsb64(qbuf + r * 100 + col, pk2(acc[nt][0], acc[nt][1]));
                stsb64(qbuf + (r + 8) * 100 + col, pk2(acc[nt][2], acc[nt][3]));
            } else if (col < 192) {
                int kc = col - 96;
                kT[kc * 68 + r] = acc[nt][0];
                kT[(kc + 1) * 68 + r] = acc[nt][1];
                kT[kc * 68 + r + 8] = acc[nt][2];
                kT[(kc + 1) * 68 + r + 8] = acc[nt][3];
            } else {
                int vc = col - 192;
                stsb64(vbuf + r * 100 + vc, pk2(acc[nt][0], acc[nt][1]));
                stsb64(vbuf + (r + 8) * 100 + vc, pk2(acc[nt][2], acc[nt][3]));
            }
        }
    }
    __syncthreads();

    float* obuf = xs;   // reuse LN1 buffer for attention output (row-major tf32)

    // ---- attention (proven inner loops; output tf32 row-major)
    {
        const int n = tid >> 3, sub = tid & 7;
        const int m0 = sub * 8;
        #pragma unroll 1
        for (int h = 0; h < NH; h++) {
            const int hb = h * HD;
            u64t qd[HD];
            #pragma unroll
            for (int dd = 0; dd < HD; dd++) qd[dd] = dup2(qbuf[n * 100 + hb + dd]);

            u64t p2[4] = {0ull, 0ull, 0ull, 0ull};
            #pragma unroll
            for (int dd = 0; dd < HD; dd++) {
                const float* kp = kT + (hb + dd) * 68 + m0;
                u64t k01, k23, k45, k67;
                ldsv2b64(k01, k23, kp);
                ldsv2b64(k45, k67, kp + 4);
                fma2(p2[0], qd[dd], k01); fma2(p2[1], qd[dd], k23);
                fma2(p2[2], qd[dd], k45); fma2(p2[3], qd[dd], k67);
            }
            float p[8];
            #pragma unroll
            for (int i = 0; i < 4; i++) { float2 t = up2(p2[i]); p[2*i] = t.x; p[2*i+1] = t.y; }
            #pragma unroll
            for (int i = 0; i < 8; i++) {
                int rdx = rel[n * 64 + m0 + i];
                p[i] = p[i] * 0.25f + sbias[rdx * NH + h];
            }
            float mx = -1e30f;
            #pragma unroll
            for (int i = 0; i < 8; i++) mx = fmaxf(mx, p[i]);
            mx = fmaxf(mx, __shfl_xor_sync(0xffffffffu, mx, 1));
            mx = fmaxf(mx, __shfl_xor_sync(0xffffffffu, mx, 2));
            mx = fmaxf(mx, __shfl_xor_sync(0xffffffffu, mx, 4));
            float sum = 0.f;
            #pragma unroll
            for (int i = 0; i < 8; i++) { p[i] = __expf(p[i] - mx); sum += p[i]; }
            sum += __shfl_xor_sync(0xffffffffu, sum, 1);
            sum += __shfl_xor_sync(0xffffffffu, sum, 2);
            sum += __shfl_xor_sync(0xffffffffu, sum, 4);
            float inv = 1.f / sum;
            #pragma unroll
            for (int i = 0; i < 8; i++) sbuf[n * 68 + m0 + i] = p[i] * inv;
            __syncwarp();

            float o0 = 0.f, o1 = 0.f, o0b = 0.f, o1b = 0.f;
            const float* vb = vbuf + hb + sub * 2;
            #pragma unroll
            for (int m4 = 0; m4 < 16; m4++) {
                float4 pr = ldsf4(sbuf + n * 68 + m4 * 4);
                const float* vm = vb + (m4 * 4) * 100;
                float2 v0 = ldsf2(vm);         o0  += pr.x * v0.x; o1  += pr.x * v0.y;
                float2 v1 = ldsf2(vm + 100);   o0b += pr.y * v1.x; o1b += pr.y * v1.y;
                float2 v2 = ldsf2(vm + 200);   o0  += pr.z * v2.x; o1  += pr.z * v2.y;
                float2 v3 = ldsf2(vm + 300);   o0b += pr.w * v3.x; o1b += pr.w * v3.y;
            }
            stsb64(obuf + n * 104 + hb + 2 * sub,
                   pk2(tf32f(o0 + o0b), tf32f(o1 + o1b)));
            __syncwarp();
        }
    }
    __syncthreads();

    // ---- stage proj_w [96][100] tf32 (one shot)
    {
        float2 t[9];
        const float* src = proj_w + tid * 18;
        #pragma unroll
        for (int i = 0; i < 9; i++) t[i] = __ldg((const float2*)(src + 2 * i));
        const float* pv = (const float*)t;
        #pragma unroll
        for (int i = 0; i < 18; i++) {
            int idx = tid * 18 + i;
            wc[(idx / 96) * 100 + (idx % 96)] = tf32f(pv[i]);
        }
    }
    __syncthreads();

    // ---- proj GEMM (m16n8k8): warp = 1 m-tile x 3 n-tiles (24 cols)
    {
        const int mt = wid & 3, ng = wid >> 2;
        const int m0 = 16 * mt, n0 = 24 * ng;
        float acc[3][4];
        #pragma unroll
        for (int nt = 0; nt < 3; nt++) {
            int col = n0 + 8 * nt + 2 * cq;
            float bx = __ldg(proj_b + col), by = __ldg(proj_b + col + 1);
            acc[nt][0] = bx; acc[nt][1] = by;
            acc[nt][2] = bx; acc[nt][3] = by;
        }
        #pragma unroll
        for (int kq = 0; kq < 12; kq++) {
            const int kloc = 8 * kq + 2 * cq;
            unsigned A[4];
            u64t lo = ldsb64(obuf + (m0 + g) * 104 + kloc);
            u64t hi = ldsb64(obuf + (m0 + g + 8) * 104 + kloc);
            A[0] = (unsigned)lo; A[2] = (unsigned)(lo >> 32);
            A[1] = (unsigned)hi; A[3] = (unsigned)(hi >> 32);
            #pragma unroll
            for (int nt = 0; nt < 3; nt++) {
                const float* wp = wc + kloc * 100 + n0 + 8 * nt + g;
                unsigned b0 = ldsu32(wp);
                unsigned b1 = ldsu32(wp + 100);
                mma8(acc[nt], A, b0, b1);
            }
        }
        // residual + scatter to g_ybuf
        int r = m0 + g;
        size_t base0 = (size_t)(bb * LTOK + srcidx[r]) * C;
        size_t base1 = (size_t)(bb * LTOK + srcidx[r + 8]) * C;
        #pragma unroll
        for (int nt = 0; nt < 3; nt++) {
            int col = n0 + 8 * nt + 2 * cq;
            float2 x0 = *(const float2*)(x + base0 + col);
            float2 x1 = *(const float2*)(x + base1 + col);
            *(float2*)(g_ybuf + base0 + col) =
                make_float2(x0.x + acc[nt][0], x0.y + acc[nt][1]);
            *(float2*)(g_ybuf + base1 + col) =
                make_float2(x1.x + acc[nt][2], x1.y + acc[nt][3]);
        }
    }
}

// ======================= Kernel B: tf32 mma MLP (R10, unchanged) ===========
#define SM_HID 0        // hid [64][392]                      (25088)
#define SM_H2S 25088    // h2s [64][104]                      (6656)
#define SM_W1C 31744    // w1 chunk [32][396]                 (12672)
#define SM_W2C 25088    // w2 chunk [64][396] (reuses h2s+w1c region, 25344)
#define B_TOT  50432

__global__ __launch_bounds__(512, 1)
void mlp_kernel(const float* __restrict__ g2, const float* __restrict__ b2,
                const float* __restrict__ w1, const float* __restrict__ bb1,
                const float* __restrict__ w2, const float* __restrict__ bb2,
                float* __restrict__ out)
{
    extern __shared__ float smf[];
    float* hid = smf + SM_HID;
    float* h2s = smf + SM_H2S;
    float* w1c = smf + SM_W1C;
    float* w2c = smf + SM_W2C;

    const int tid = threadIdx.x;
    const int t0 = blockIdx.x * NW;
    const int lane = tid & 31, wid = tid >> 5;
    const int g = lane >> 2, cq = lane & 3;

    float4 wpf[6];
    {
        const float* src = w1 + tid * 24;
        #pragma unroll
        for (int i = 0; i < 6; i++) wpf[i] = __ldg((const float4*)(src + 4 * i));
    }

    // ---- LN2 -> h2s[n][104]
    {
        const int n = tid >> 3, q8 = tid & 7;
        const float* yr = g_ybuf + (size_t)(t0 + n) * C + q8 * 12;
        float v[12]; float s = 0.f, ss = 0.f;
        #pragma unroll
        for (int j = 0; j < 12; j++) { float t = yr[j]; v[j] = t; s += t; ss += t * t; }
        s  += __shfl_xor_sync(0xffffffffu, s, 1);  ss += __shfl_xor_sync(0xffffffffu, ss, 1);
        s  += __shfl_xor_sync(0xffffffffu, s, 2);  ss += __shfl_xor_sync(0xffffffffu, ss, 2);
        s  += __shfl_xor_sync(0xffffffffu, s, 4);  ss += __shfl_xor_sync(0xffffffffu, ss, 4);
        float mean = s * (1.f / 96.f);
        float var  = ss * (1.f / 96.f) - mean * mean;
        float rstd = rsqrtf(var + 1e-5f);
        #pragma unroll
        for (int j = 0; j < 12; j++) {
            int c = q8 * 12 + j;
            float val = (v[j] - mean) * rstd * __ldg(g2 + c) + __ldg(b2 + c);
            h2s[n * 104 + c] = tf32f(val);
        }
    }

    // ---- GEMM1 (m16n8k8): warp = 2 m-tiles x 6 n-tiles
    const int mh = wid & 1, ng = wid >> 1;
    const int m0 = 32 * mh, n0 = 48 * ng;
    float acc1[2][6][4];
    #pragma unroll
    for (int nt = 0; nt < 6; nt++) {
        int col = n0 + 8 * nt + 2 * cq;
        float bx = __ldg(bb1 + col), by = __ldg(bb1 + col + 1);
        #pragma unroll
        for (int mi = 0; mi < 2; mi++) {
            acc1[mi][nt][0] = bx; acc1[mi][nt][1] = by;
            acc1[mi][nt][2] = bx; acc1[mi][nt][3] = by;
        }
    }
    {
        int kk = (tid * 24) / 384, nn = (tid * 24) % 384;
        float* d = w1c + kk * 396 + nn;
        const float* pv = (const float*)wpf;
        #pragma unroll
        for (int i = 0; i < 24; i++) d[i] = tf32f(pv[i]);
    }
    __syncthreads();

    #pragma unroll 1
    for (int c3 = 0; c3 < 3; c3++) {
        if (c3 < 2) {
            const float* src = w1 + (c3 + 1) * 12288 + tid * 24;
            #pragma unroll
            for (int i = 0; i < 6; i++) wpf[i] = __ldg((const float4*)(src + 4 * i));
        }
        #pragma unroll
        for (int kq = 0; kq < 4; kq++) {
            const int kb = 8 * kq;
            const int kA = 32 * c3 + kb + 2 * cq;
            unsigned A[2][4];
            #pragma unroll
            for (int mi = 0; mi < 2; mi++) {
                int row = m0 + 16 * mi + g;
                u64t lo = ldsb64(h2s + row * 104 + kA);
                u64t hi = ldsb64(h2s + (row + 8) * 104 + kA);
                A[mi][0] = (unsigned)lo; A[mi][2] = (unsigned)(lo >> 32);
                A[mi][1] = (unsigned)hi; A[mi][3] = (unsigned)(hi >> 32);
            }
            #pragma unroll
            for (int nt = 0; nt < 6; nt++) {
                const float* wp = w1c + (kb + 2 * cq) * 396 + n0 + 8 * nt + g;
                unsigned b0 = ldsu32(wp);
                unsigned b1 = ldsu32(wp + 396);
                mma8(acc1[0][nt], A[0], b0, b1);
                mma8(acc1[1][nt], A[1], b0, b1);
            }
        }
        __syncthreads();
        if (c3 < 2) {
            int kk = (tid * 24) / 384, nn = (tid * 24) % 384;
            float* d = w1c + kk * 396 + nn;
            const float* pv = (const float*)wpf;
            #pragma unroll
            for (int i = 0; i < 24; i++) d[i] = tf32f(pv[i]);
            __syncthreads();
        }
    }

    // GELU + tf32 -> hid[64][392]
    #pragma unroll
    for (int mi = 0; mi < 2; mi++) {
        #pragma unroll
        for (int nt = 0; nt < 6; nt++) {
            int row = m0 + 16 * mi + g;
            int col = n0 + 8 * nt + 2 * cq;
            float* a = acc1[mi][nt];
            float g0 = 0.5f * a[0] * (1.0f + erff(a[0] * 0.70710678118654752f));
            float g1 = 0.5f * a[1] * (1.0f + erff(a[1] * 0.70710678118654752f));
            float g2v = 0.5f * a[2] * (1.0f + erff(a[2] * 0.70710678118654752f));
            float g3 = 0.5f * a[3] * (1.0f + erff(a[3] * 0.70710678118654752f));
            stsb64(hid + row * 392 + col, pk2(tf32f(g0), tf32f(g1)));
            stsb64(hid + (row + 8) * 392 + col, pk2(tf32f(g2v), tf32f(g3)));
        }
    }

    // ---- GEMM2 (m16n8k8): 6 chunks of 64 k
    const int mt = wid & 3, n3 = wid >> 2;
    const int m0b = 16 * mt, n0b = 24 * n3;
    float acc2[3][4];
    #pragma unroll
    for (int nt = 0; nt < 3; nt++) {
        int col = n0b + 8 * nt + 2 * cq;
        float bx = __ldg(bb2 + col), by = __ldg(bb2 + col + 1);
        acc2[nt][0] = bx; acc2[nt][1] = by;
        acc2[nt][2] = bx; acc2[nt][3] = by;
    }
    float4 wpf2[3];
    {
        const float* src = w2 + tid * 12;
        #pragma unroll
        for (int i = 0; i < 3; i++) wpf2[i] = __ldg((const float4*)(src + 4 * i));
    }
    __syncthreads();

    #pragma unroll 1
    for (int ch = 0; ch < 6; ch++) {
        {
            int base = tid * 12;
            int kk = base / 96, nn = base % 96;
            float* d = w2c + kk * 396 + nn;
            const float* pv = (const float*)wpf2;
            #pragma unroll
            for (int i = 0; i < 12; i++) d[i] = tf32f(pv[i]);
        }
        __syncthreads();
        if (ch < 5) {
            const float* src = w2 + (ch + 1) * 6144 + tid * 12;
            #pragma unroll
            for (int i = 0; i < 3; i++) wpf2[i] = __ldg((const float4*)(src + 4 * i));
        }
        #pragma unroll
        for (int kq = 0; kq < 8; kq++) {
            const int kb = 8 * kq;
            const int kA = 64 * ch + kb + 2 * cq;
            unsigned A[4];
            u64t lo = ldsb64(hid + (m0b + g) * 392 + kA);
            u64t hi = ldsb64(hid + (m0b + g + 8) * 392 + kA);
            A[0] = (unsigned)lo; A[2] = (unsigned)(lo >> 32);
            A[1] = (unsigned)hi; A[3] = (unsigned)(hi >> 32);
            #pragma unroll
            for (int nt = 0; nt < 3; nt++) {
                const float* wp = w2c + (kb + 2 * cq) * 396 + n0b + 8 * nt + g;
                unsigned b0 = ldsu32(wp);
                unsigned b1 = ldsu32(wp + 396);
                mma8(acc2[nt], A, b0, b1);
            }
        }
        __syncthreads();
    }

    // epilogue: residual + store
    #pragma unroll
    for (int nt = 0; nt < 3; nt++) {
        int col = n0b + 8 * nt + 2 * cq;
        int r0 = t0 + m0b + g;
        const float2 y0 = *(const float2*)(g_ybuf + (size_t)r0 * C + col);
        const float2 y1 = *(const float2*)(g_ybuf + (size_t)(r0 + 8) * C + col);
        float2 o0 = make_float2(y0.x + acc2[nt][0], y0.y + acc2[nt][1]);
        float2 o1 = make_float2(y1.x + acc2[nt][2], y1.y + acc2[nt][3]);
        *(float2*)(out + (size_t)r0 * C + col) = o0;
        *(float2*)(out + (size_t)(r0 + 8) * C + col) = o1;
    }
}

// ---------------------------------------------------------------------------
extern "C" void kernel_launch(void* const* d_in, const int* in_sizes, int n_in,
                              void* d_out, int out_size)
{
    const float* x        = (const float*)d_in[0];
    const float* norm1_g  = (const float*)d_in[1];
    const float* norm1_b  = (const float*)d_in[2];
    const float* qkv_w    = (const float*)d_in[3];
    const float* qkv_b    = (const float*)d_in[4];
    const float* proj_w   = (const float*)d_in[5];
    const float* proj_b   = (const float*)d_in[6];
    const float* bias_tab = (const float*)d_in[7];
    const float* norm2_g  = (const float*)d_in[8];
    const float* norm2_b  = (const float*)d_in[9];
    const float* mlp_w1   = (const float*)d_in[10];
    const float* mlp_b1   = (const float*)d_in[11];
    const float* mlp_w2   = (const float*)d_in[12];
    const float* mlp_b2   = (const float*)d_in[13];
    float* out = (float*)d_out;

    cudaFuncSetAttribute(win_attn_kernel,
                         cudaFuncAttributeMaxDynamicSharedMemorySize, A_TOT * 4);
    cudaFuncSetAttribute(mlp_kernel,
                         cudaFuncAttributeMaxDynamicSharedMemorySize, B_TOT * 4);

    win_attn_kernel<<<NTILE, 512, A_TOT * 4>>>(x, norm1_g, norm1_b,
                                               qkv_w, qkv_b, proj_w, proj_b,
                                               bias_tab);
    mlp_kernel<<<NTILE, 512, B_TOT * 4>>>(norm2_g, norm2_b,
                                          mlp_w1, mlp_b1, mlp_w2, mlp_b2, out);
}

// round 12
// speedup vs baseline: 3.4600x; 1.3573x over previous
#include <cuda_runtime.h>
#include <math.h>

// ---------------------------------------------------------------------------
// SwinTransformerBlock3D — tf32 m16n8k8 for QKV/proj/MLP AND attention QK^T/AV
// ---------------------------------------------------------------------------

#define LTOK (16*64*64)
#define BATCH 2
#define C 96
#define NH 6
#define HD 16
#define NW 64
#define MLPH 384
#define NTILE 2048

typedef unsigned long long u64t;

__device__ float g_ybuf[(size_t)BATCH * LTOK * C];

// ---------------- helpers --------------------------------------------------
__device__ __forceinline__ unsigned sp(const void* p) {
    return (unsigned)__cvta_generic_to_shared(p);
}
__device__ __forceinline__ u64t ldsb64(const float* p) {
    u64t v; asm volatile("ld.shared.b64 %0,[%1];" : "=l"(v) : "r"(sp(p))); return v;
}
__device__ __forceinline__ float4 ldsf4(const float* p) {
    float4 r; asm volatile("ld.shared.v4.f32 {%0,%1,%2,%3},[%4];"
                           : "=f"(r.x),"=f"(r.y),"=f"(r.z),"=f"(r.w) : "r"(sp(p))); return r;
}
__device__ __forceinline__ unsigned ldsu32(const float* p) {
    unsigned v; asm volatile("ld.shared.b32 %0,[%1];" : "=r"(v) : "r"(sp(p))); return v;
}
__device__ __forceinline__ void stsb64(float* p, u64t v) {
    asm volatile("st.shared.b64 [%0],%1;" :: "r"(sp(p)), "l"(v));
}
__device__ __forceinline__ u64t pk2(float x, float y) {
    u64t r; asm("mov.b64 %0,{%1,%2};" : "=l"(r) : "f"(x), "f"(y)); return r;
}
__device__ __forceinline__ float tf32f(float x) {
    unsigned r; asm("cvt.rna.tf32.f32 %0,%1;" : "=r"(r) : "f"(x));
    return __uint_as_float(r);
}
__device__ __forceinline__ void mma8(float* d, const unsigned* a,
                                     unsigned b0, unsigned b1) {
    asm("mma.sync.aligned.m16n8k8.row.col.f32.tf32.tf32.f32 "
        "{%0,%1,%2,%3},{%4,%5,%6,%7},{%8,%9},{%0,%1,%2,%3};"
        : "+f"(d[0]), "+f"(d[1]), "+f"(d[2]), "+f"(d[3])
        : "r"(a[0]), "r"(a[1]), "r"(a[2]), "r"(a[3]), "r"(b0), "r"(b1));
}

// ======================= Kernel A ==========================================
// smem float offsets (strides chosen conflict-free: 104,70,72,100 — see notes)
#define A_XS   0        // xs [64][104] tf32 LN1; reused as obuf [64][104]
#define A_Q    6656     // qbuf [64][104]
#define A_KT   13312    // kT [96][70]
#define A_V    20032    // vbuf [64][100]
#define A_S    26432    // sbuf [64][72]
#define A_WC   31040    // qkv chunk [32][292] (9344) / proj_w [96][100] (9600)
#define A_BIAS 40640    // 2058
#define A_REL  42698    // u16[4096] = 2048 floats
#define A_SRC  44746    // int[64]
#define A_TOT  44810

__global__ __launch_bounds__(512, 1)
void win_attn_kernel(const float* __restrict__ x,
                     const float* __restrict__ g1, const float* __restrict__ b1,
                     const float* __restrict__ qkv_w, const float* __restrict__ qkv_b,
                     const float* __restrict__ proj_w, const float* __restrict__ proj_b,
                     const float* __restrict__ bias_table)
{
    extern __shared__ float smf[];
    float* xs   = smf + A_XS;
    float* qbuf = smf + A_Q;
    float* kT   = smf + A_KT;
    float* vbuf = smf + A_V;
    float* sbuf = smf + A_S;
    float* wc   = smf + A_WC;
    float* sbias = smf + A_BIAS;
    unsigned short* rel = (unsigned short*)(smf + A_REL);
    int* srcidx = (int*)(smf + A_SRC);

    const int tid = threadIdx.x;
    const int lane = tid & 31, wid = tid >> 5;
    const int g = lane >> 2, cq = lane & 3;
    const int wb = blockIdx.x;
    const int bb = wb >> 10;
    const int w  = wb & 1023;
    const int iw = w >> 8, xw = (w >> 4) & 15, tw = w & 15;

    // prefetch qkv_w chunk 0 (32x288 = 9216 floats; 18/thread, row-aligned)
    float2 wpf[9];
    {
        const float* src = qkv_w + tid * 18;
        #pragma unroll
        for (int i = 0; i < 9; i++) wpf[i] = __ldg((const float2*)(src + 2 * i));
    }

    if (tid < NW) {
        int i = tid >> 4, xx = (tid >> 2) & 3, tt = tid & 3;
        int gi = (iw * 4 + i  + 2) & 15;
        int gx = (xw * 4 + xx + 2) & 63;
        int gt = (tw * 4 + tt + 2) & 63;
        srcidx[tid] = ((gi << 6) + gx) * 64 + gt;
    }
    for (int p = tid; p < 4096; p += 512) {
        int n = p >> 6, m = p & 63;
        int di = (n >> 4)       - (m >> 4)       + 3;
        int dx = ((n >> 2) & 3) - ((m >> 2) & 3) + 3;
        int dt = (n & 3)        - (m & 3)        + 3;
        rel[p] = (unsigned short)((di * 7 + dx) * 7 + dt);
    }
    for (int i = tid; i < 343 * NH; i += 512) sbias[i] = __ldg(bias_table + i);
    __syncthreads();

    // ---- LN1 -> xs[n][104] (tf32)
    {
        const int n = tid >> 3, q8 = tid & 7;
        const float* xr = x + ((size_t)(bb * LTOK + srcidx[n])) * C + q8 * 12;
        float v[12]; float s = 0.f, ss = 0.f;
        #pragma unroll
        for (int j = 0; j < 12; j++) { float t = xr[j]; v[j] = t; s += t; ss += t * t; }
        s  += __shfl_xor_sync(0xffffffffu, s, 1);  ss += __shfl_xor_sync(0xffffffffu, ss, 1);
        s  += __shfl_xor_sync(0xffffffffu, s, 2);  ss += __shfl_xor_sync(0xffffffffu, ss, 2);
        s  += __shfl_xor_sync(0xffffffffu, s, 4);  ss += __shfl_xor_sync(0xffffffffu, ss, 4);
        float mean = s * (1.f / 96.f);
        float var  = ss * (1.f / 96.f) - mean * mean;
        float rstd = rsqrtf(var + 1e-5f);
        #pragma unroll
        for (int j = 0; j < 12; j++) {
            int c = q8 * 12 + j;
            float val = (v[j] - mean) * rstd * __ldg(g1 + c) + __ldg(b1 + c);
            xs[n * 104 + c] = tf32f(val);
        }
    }

    // ---- QKV GEMM (m16n8k8): warp = 1 m-tile x 9 n-tiles (72 cols)
    {
        const int mt = wid & 3, ng = wid >> 2;
        const int m0 = 16 * mt, n0 = 72 * ng;
        float acc[9][4];
        #pragma unroll
        for (int nt = 0; nt < 9; nt++) {
            int col = n0 + 8 * nt + 2 * cq;
            float bx = __ldg(qkv_b + col), by = __ldg(qkv_b + col + 1);
            acc[nt][0] = bx; acc[nt][1] = by;
            acc[nt][2] = bx; acc[nt][3] = by;
        }
        {   // stage chunk 0
            int kk = tid >> 4, nn = (tid & 15) * 18;
            float* d = wc + kk * 292 + nn;
            const float* pv = (const float*)wpf;
            #pragma unroll
            for (int i = 0; i < 18; i++) d[i] = tf32f(pv[i]);
        }
        __syncthreads();

        #pragma unroll 1
        for (int c3 = 0; c3 < 3; c3++) {
            if (c3 < 2) {
                const float* src = qkv_w + (c3 + 1) * 9216 + tid * 18;
                #pragma unroll
                for (int i = 0; i < 9; i++) wpf[i] = __ldg((const float2*)(src + 2 * i));
            }
            #pragma unroll
            for (int kq = 0; kq < 4; kq++) {
                const int kloc = 8 * kq + 2 * cq;
                const int kA = 32 * c3 + kloc;
                unsigned A[4];
                u64t lo = ldsb64(xs + (m0 + g) * 104 + kA);
                u64t hi = ldsb64(xs + (m0 + g + 8) * 104 + kA);
                A[0] = (unsigned)lo; A[2] = (unsigned)(lo >> 32);
                A[1] = (unsigned)hi; A[3] = (unsigned)(hi >> 32);
                #pragma unroll
                for (int nt = 0; nt < 9; nt++) {
                    const float* wp = wc + kloc * 292 + n0 + 8 * nt + g;
                    unsigned b0 = ldsu32(wp);
                    unsigned b1 = ldsu32(wp + 292);
                    mma8(acc[nt], A, b0, b1);
                }
            }
            __syncthreads();
            if (c3 < 2) {
                int kk = tid >> 4, nn = (tid & 15) * 18;
                float* d = wc + kk * 292 + nn;
                const float* pv = (const float*)wpf;
                #pragma unroll
                for (int i = 0; i < 18; i++) d[i] = tf32f(pv[i]);
                __syncthreads();
            }
        }

        // scatter fragments (tf32-rounded) to qbuf / kT / vbuf
        #pragma unroll
        for (int nt = 0; nt < 9; nt++) {
            int col = n0 + 8 * nt + 2 * cq;
            int r = m0 + g;
            if (col < 96) {
                stsb64(qbuf + r * 104 + col, pk2(tf32f(acc[nt][0]), tf32f(acc[nt][1])));
                stsb64(qbuf + (r + 8) * 104 + col, pk2(tf32f(acc[nt][2]), tf32f(acc[nt][3])));
            } else if (col < 192) {
                int kc = col - 96;
                kT[kc * 70 + r] = tf32f(acc[nt][0]);
                kT[(kc + 1) * 70 + r] = tf32f(acc[nt][1]);
                kT[kc * 70 + r + 8] = tf32f(acc[nt][2]);
                kT[(kc + 1) * 70 + r + 8] = tf32f(acc[nt][3]);
            } else {
                int vc = col - 192;
                stsb64(vbuf + r * 100 + vc, pk2(tf32f(acc[nt][0]), tf32f(acc[nt][1])));
                stsb64(vbuf + (r + 8) * 100 + vc, pk2(tf32f(acc[nt][2]), tf32f(acc[nt][3])));
            }
        }
    }
    __syncthreads();

    float* obuf = xs;   // reuse LN1 buffer for attention output

    // ---- attention: per head, QK^T mma -> scalar softmax -> AV mma
    #pragma unroll 1
    for (int h = 0; h < NH; h++) {
        const int hb = h * HD;

        // QK^T: 16 warps, warp = m-tile (wid&3) x 2 n-tiles (wid>>2)
        {
            const int mt2 = wid & 3, nh4 = wid >> 2;
            const int r = 16 * mt2 + g;
            float acc[2][4] = {{0.f,0.f,0.f,0.f},{0.f,0.f,0.f,0.f}};
            #pragma unroll
            for (int kq = 0; kq < 2; kq++) {
                int kd = 8 * kq + 2 * cq;
                u64t lo = ldsb64(qbuf + r * 104 + hb + kd);
                u64t hi = ldsb64(qbuf + (r + 8) * 104 + hb + kd);
                unsigned A[4];
                A[0] = (unsigned)lo; A[2] = (unsigned)(lo >> 32);
                A[1] = (unsigned)hi; A[3] = (unsigned)(hi >> 32);
                #pragma unroll
                for (int t = 0; t < 2; t++) {
                    int mcol = 8 * (2 * nh4 + t) + g;
                    unsigned b0 = ldsu32(kT + (hb + kd) * 70 + mcol);
                    unsigned b1 = ldsu32(kT + (hb + kd + 1) * 70 + mcol);
                    mma8(acc[t], A, b0, b1);
                }
            }
            #pragma unroll
            for (int t = 0; t < 2; t++) {
                int col = 8 * (2 * nh4 + t) + 2 * cq;
                float s00 = acc[t][0] * 0.25f + sbias[rel[r * 64 + col] * NH + h];
                float s01 = acc[t][1] * 0.25f + sbias[rel[r * 64 + col + 1] * NH + h];
                float s10 = acc[t][2] * 0.25f + sbias[rel[(r + 8) * 64 + col] * NH + h];
                float s11 = acc[t][3] * 0.25f + sbias[rel[(r + 8) * 64 + col + 1] * NH + h];
                stsb64(sbuf + r * 72 + col, pk2(s00, s01));
                stsb64(sbuf + (r + 8) * 72 + col, pk2(s10, s11));
            }
        }
        __syncthreads();

        // softmax: row n = tid>>3, 8 cols per thread (proven pattern)
        {
            const int n = tid >> 3, m0s = (tid & 7) * 8;
            float4 pa = ldsf4(sbuf + n * 72 + m0s);
            float4 pb = ldsf4(sbuf + n * 72 + m0s + 4);
            float p[8] = {pa.x, pa.y, pa.z, pa.w, pb.x, pb.y, pb.z, pb.w};
            float mx = -1e30f;
            #pragma unroll
            for (int i = 0; i < 8; i++) mx = fmaxf(mx, p[i]);
            mx = fmaxf(mx, __shfl_xor_sync(0xffffffffu, mx, 1));
            mx = fmaxf(mx, __shfl_xor_sync(0xffffffffu, mx, 2));
            mx = fmaxf(mx, __shfl_xor_sync(0xffffffffu, mx, 4));
            float sum = 0.f;
            #pragma unroll
            for (int i = 0; i < 8; i++) { p[i] = __expf(p[i] - mx); sum += p[i]; }
            sum += __shfl_xor_sync(0xffffffffu, sum, 1);
            sum += __shfl_xor_sync(0xffffffffu, sum, 2);
            sum += __shfl_xor_sync(0xffffffffu, sum, 4);
            float inv = 1.f / sum;
            #pragma unroll
            for (int i = 0; i < 4; i++)
                stsb64(sbuf + n * 72 + m0s + 2 * i,
                       pk2(tf32f(p[2 * i] * inv), tf32f(p[2 * i + 1] * inv)));
        }
        __syncthreads();

        // AV: warps 0..7, warp = m-tile (wid>>1) x n-tile (wid&1)
        if (wid < 8) {
            const int mt2 = wid >> 1, ntv = wid & 1;
            const int r = 16 * mt2 + g;
            float acc[4] = {0.f, 0.f, 0.f, 0.f};
            #pragma unroll
            for (int kq = 0; kq < 8; kq++) {
                int km = 8 * kq + 2 * cq;
                u64t lo = ldsb64(sbuf + r * 72 + km);
                u64t hi = ldsb64(sbuf + (r + 8) * 72 + km);
                unsigned A[4];
                A[0] = (unsigned)lo; A[2] = (unsigned)(lo >> 32);
                A[1] = (unsigned)hi; A[3] = (unsigned)(hi >> 32);
                unsigned b0 = ldsu32(vbuf + km * 100 + hb + 8 * ntv + g);
                unsigned b1 = ldsu32(vbuf + (km + 1) * 100 + hb + 8 * ntv + g);
                mma8(acc, A, b0, b1);
            }
            stsb64(obuf + r * 104 + hb + 8 * ntv + 2 * cq,
                   pk2(tf32f(acc[0]), tf32f(acc[1])));
            stsb64(obuf + (r + 8) * 104 + hb + 8 * ntv + 2 * cq,
                   pk2(tf32f(acc[2]), tf32f(acc[3])));
        }
        __syncthreads();
    }

    // ---- stage proj_w [96][100] tf32 (one shot)
    {
        float2 t[9];
        const float* src = proj_w + tid * 18;
        #pragma unroll
        for (int i = 0; i < 9; i++) t[i] = __ldg((const float2*)(src + 2 * i));
        const float* pv = (const float*)t;
        #pragma unroll
        for (int i = 0; i < 18; i++) {
            int idx = tid * 18 + i;
            wc[(idx / 96) * 100 + (idx % 96)] = tf32f(pv[i]);
        }
    }
    __syncthreads();

    // ---- proj GEMM (m16n8k8): warp = 1 m-tile x 3 n-tiles (24 cols)
    {
        const int mt = wid & 3, ng = wid >> 2;
        const int m0 = 16 * mt, n0 = 24 * ng;
        float acc[3][4];
        #pragma unroll
        for (int nt = 0; nt < 3; nt++) {
            int col = n0 + 8 * nt + 2 * cq;
            float bx = __ldg(proj_b + col), by = __ldg(proj_b + col + 1);
            acc[nt][0] = bx; acc[nt][1] = by;
            acc[nt][2] = bx; acc[nt][3] = by;
        }
        #pragma unroll
        for (int kq = 0; kq < 12; kq++) {
            const int kloc = 8 * kq + 2 * cq;
            unsigned A[4];
            u64t lo = ldsb64(obuf + (m0 + g) * 104 + kloc);
            u64t hi = ldsb64(obuf + (m0 + g + 8) * 104 + kloc);
            A[0] = (unsigned)lo; A[2] = (unsigned)(lo >> 32);
            A[1] = (unsigned)hi; A[3] = (unsigned)(hi >> 32);
            #pragma unroll
            for (int nt = 0; nt < 3; nt++) {
                const float* wp = wc + kloc * 100 + n0 + 8 * nt + g;
                unsigned b0 = ldsu32(wp);
                unsigned b1 = ldsu32(wp + 100);
                mma8(acc[nt], A, b0, b1);
            }
        }
        int r = m0 + g;
        size_t base0 = (size_t)(bb * LTOK + srcidx[r]) * C;
        size_t base1 = (size_t)(bb * LTOK + srcidx[r + 8]) * C;
        #pragma unroll
        for (int nt = 0; nt < 3; nt++) {
            int col = n0 + 8 * nt + 2 * cq;
            float2 x0 = *(const float2*)(x + base0 + col);
            float2 x1 = *(const float2*)(x + base1 + col);
            *(float2*)(g_ybuf + base0 + col) =
                make_float2(x0.x + acc[nt][0], x0.y + acc[nt][1]);
            *(float2*)(g_ybuf + base1 + col) =
                make_float2(x1.x + acc[nt][2], x1.y + acc[nt][3]);
        }
    }
}

// ======================= Kernel B: tf32 mma MLP (R10/R11, unchanged) =======
#define SM_HID 0        // hid [64][392]                      (25088)
#define SM_H2S 25088    // h2s [64][104]                      (6656)
#define SM_W1C 31744    // w1 chunk [32][396]                 (12672)
#define SM_W2C 25088    // w2 chunk [64][396] (reuses h2s+w1c region, 25344)
#define B_TOT  50432

__global__ __launch_bounds__(512, 1)
void mlp_kernel(const float* __restrict__ g2, const float* __restrict__ b2,
                const float* __restrict__ w1, const float* __restrict__ bb1,
                const float* __restrict__ w2, const float* __restrict__ bb2,
                float* __restrict__ out)
{
    extern __shared__ float smf[];
    float* hid = smf + SM_HID;
    float* h2s = smf + SM_H2S;
    float* w1c = smf + SM_W1C;
    float* w2c = smf + SM_W2C;

    const int tid = threadIdx.x;
    const int t0 = blockIdx.x * NW;
    const int lane = tid & 31, wid = tid >> 5;
    const int g = lane >> 2, cq = lane & 3;

    float4 wpf[6];
    {
        const float* src = w1 + tid * 24;
        #pragma unroll
        for (int i = 0; i < 6; i++) wpf[i] = __ldg((const float4*)(src + 4 * i));
    }

    // ---- LN2 -> h2s[n][104]
    {
        const int n = tid >> 3, q8 = tid & 7;
        const float* yr = g_ybuf + (size_t)(t0 + n) * C + q8 * 12;
        float v[12]; float s = 0.f, ss = 0.f;
        #pragma unroll
        for (int j = 0; j < 12; j++) { float t = yr[j]; v[j] = t; s += t; ss += t * t; }
        s  += __shfl_xor_sync(0xffffffffu, s, 1);  ss += __shfl_xor_sync(0xffffffffu, ss, 1);
        s  += __shfl_xor_sync(0xffffffffu, s, 2);  ss += __shfl_xor_sync(0xffffffffu, ss, 2);
        s  += __shfl_xor_sync(0xffffffffu, s, 4);  ss += __shfl_xor_sync(0xffffffffu, ss, 4);
        float mean = s * (1.f / 96.f);
        float var  = ss * (1.f / 96.f) - mean * mean;
        float rstd = rsqrtf(var + 1e-5f);
        #pragma unroll
        for (int j = 0; j < 12; j++) {
            int c = q8 * 12 + j;
            float val = (v[j] - mean) * rstd * __ldg(g2 + c) + __ldg(b2 + c);
            h2s[n * 104 + c] = tf32f(val);
        }
    }

    // ---- GEMM1 (m16n8k8): warp = 2 m-tiles x 6 n-tiles
    const int mh = wid & 1, ng = wid >> 1;
    const int m0 = 32 * mh, n0 = 48 * ng;
    float acc1[2][6][4];
    #pragma unroll
    for (int nt = 0; nt < 6; nt++) {
        int col = n0 + 8 * nt + 2 * cq;
        float bx = __ldg(bb1 + col), by = __ldg(bb1 + col + 1);
        #pragma unroll
        for (int mi = 0; mi < 2; mi++) {
            acc1[mi][nt][0] = bx; acc1[mi][nt][1] = by;
            acc1[mi][nt][2] = bx; acc1[mi][nt][3] = by;
        }
    }
    {
        int kk = (tid * 24) / 384, nn = (tid * 24) % 384;
        float* d = w1c + kk * 396 + nn;
        const float* pv = (const float*)wpf;
        #pragma unroll
        for (int i = 0; i < 24; i++) d[i] = tf32f(pv[i]);
    }
    __syncthreads();

    #pragma unroll 1
    for (int c3 = 0; c3 < 3; c3++) {
        if (c3 < 2) {
            const float* src = w1 + (c3 + 1) * 12288 + tid * 24;
            #pragma unroll
            for (int i = 0; i < 6; i++) wpf[i] = __ldg((const float4*)(src + 4 * i));
        }
        #pragma unroll
        for (int kq = 0; kq < 4; kq++) {
            const int kb = 8 * kq;
            const int kA = 32 * c3 + kb + 2 * cq;
            unsigned A[2][4];
            #pragma unroll
            for (int mi = 0; mi < 2; mi++) {
                int row = m0 + 16 * mi + g;
                u64t lo = ldsb64(h2s + row * 104 + kA);
                u64t hi = ldsb64(h2s + (row + 8) * 104 + kA);
                A[mi][0] = (unsigned)lo; A[mi][2] = (unsigned)(lo >> 32);
                A[mi][1] = (unsigned)hi; A[mi][3] = (unsigned)(hi >> 32);
            }
            #pragma unroll
            for (int nt = 0; nt < 6; nt++) {
                const float* wp = w1c + (kb + 2 * cq) * 396 + n0 + 8 * nt + g;
                unsigned b0 = ldsu32(wp);
                unsigned b1 = ldsu32(wp + 396);
                mma8(acc1[0][nt], A[0], b0, b1);
                mma8(acc1[1][nt], A[1], b0, b1);
            }
        }
        __syncthreads();
        if (c3 < 2) {
            int kk = (tid * 24) / 384, nn = (tid * 24) % 384;
            float* d = w1c + kk * 396 + nn;
            const float* pv = (const float*)wpf;
            #pragma unroll
            for (int i = 0; i < 24; i++) d[i] = tf32f(pv[i]);
            __syncthreads();
        }
    }

    // GELU + tf32 -> hid[64][392]
    #pragma unroll
    for (int mi = 0; mi < 2; mi++) {
        #pragma unroll
        for (int nt = 0; nt < 6; nt++) {
            int row = m0 + 16 * mi + g;
            int col = n0 + 8 * nt + 2 * cq;
            float* a = acc1[mi][nt];
            float g0 = 0.5f * a[0] * (1.0f + erff(a[0] * 0.70710678118654752f));
            float g1 = 0.5f * a[1] * (1.0f + erff(a[1] * 0.70710678118654752f));
            float g2v = 0.5f * a[2] * (1.0f + erff(a[2] * 0.70710678118654752f));
            float g3 = 0.5f * a[3] * (1.0f + erff(a[3] * 0.70710678118654752f));
            stsb64(hid + row * 392 + col, pk2(tf32f(g0), tf32f(g1)));
            stsb64(hid + (row + 8) * 392 + col, pk2(tf32f(g2v), tf32f(g3)));
        }
    }

    // ---- GEMM2 (m16n8k8): 6 chunks of 64 k
    const int mt = wid & 3, n3 = wid >> 2;
    const int m0b = 16 * mt, n0b = 24 * n3;
    float acc2[3][4];
    #pragma unroll
    for (int nt = 0; nt < 3; nt++) {
        int col = n0b + 8 * nt + 2 * cq;
        float bx = __ldg(bb2 + col), by = __ldg(bb2 + col + 1);
        acc2[nt][0] = bx; acc2[nt][1] = by;
        acc2[nt][2] = bx; acc2[nt][3] = by;
    }
    float4 wpf2[3];
    {
        const float* src = w2 + tid * 12;
        #pragma unroll
        for (int i = 0; i < 3; i++) wpf2[i] = __ldg((const float4*)(src + 4 * i));
    }
    __syncthreads();

    #pragma unroll 1
    for (int ch = 0; ch < 6; ch++) {
        {
            int base = tid * 12;
            int kk = base / 96, nn = base % 96;
            float* d = w2c + kk * 396 + nn;
            const float* pv = (const float*)wpf2;
            #pragma unroll
            for (int i = 0; i < 12; i++) d[i] = tf32f(pv[i]);
        }
        __syncthreads();
        if (ch < 5) {
            const float* src = w2 + (ch + 1) * 6144 + tid * 12;
            #pragma unroll
            for (int i = 0; i < 3; i++) wpf2[i] = __ldg((const float4*)(src + 4 * i));
        }
        #pragma unroll
        for (int kq = 0; kq < 8; kq++) {
            const int kb = 8 * kq;
            const int kA = 64 * ch + kb + 2 * cq;
            unsigned A[4];
            u64t lo = ldsb64(hid + (m0b + g) * 392 + kA);
            u64t hi = ldsb64(hid + (m0b + g + 8) * 392 + kA);
            A[0] = (unsigned)lo; A[2] = (unsigned)(lo >> 32);
            A[1] = (unsigned)hi; A[3] = (unsigned)(hi >> 32);
            #pragma unroll
            for (int nt = 0; nt < 3; nt++) {
                const float* wp = w2c + (kb + 2 * cq) * 396 + n0b + 8 * nt + g;
                unsigned b0 = ldsu32(wp);
                unsigned b1 = ldsu32(wp + 396);
                mma8(acc2[nt], A, b0, b1);
            }
        }
        __syncthreads();
    }

    // epilogue: residual + store
    #pragma unroll
    for (int nt = 0; nt < 3; nt++) {
        int col = n0b + 8 * nt + 2 * cq;
        int r0 = t0 + m0b + g;
        const float2 y0 = *(const float2*)(g_ybuf + (size_t)r0 * C + col);
        const float2 y1 = *(const float2*)(g_ybuf + (size_t)(r0 + 8) * C + col);
        float2 o0 = make_float2(y0.x + acc2[nt][0], y0.y + acc2[nt][1]);
        float2 o1 = make_float2(y1.x + acc2[nt][2], y1.y + acc2[nt][3]);
        *(float2*)(out + (size_t)r0 * C + col) = o0;
        *(float2*)(out + (size_t)(r0 + 8) * C + col) = o1;
    }
}

// ---------------------------------------------------------------------------
extern "C" void kernel_launch(void* const* d_in, const int* in_sizes, int n_in,
                              void* d_out, int out_size)
{
    const float* x        = (const float*)d_in[0];
    const float* norm1_g  = (const float*)d_in[1];
    const float* norm1_b  = (const float*)d_in[2];
    const float* qkv_w    = (const float*)d_in[3];
    const float* qkv_b    = (const float*)d_in[4];
    const float* proj_w   = (const float*)d_in[5];
    const float* proj_b   = (const float*)d_in[6];
    const float* bias_tab = (const float*)d_in[7];
    const float* norm2_g  = (const float*)d_in[8];
    const float* norm2_b  = (const float*)d_in[9];
    const float* mlp_w1   = (const float*)d_in[10];
    const float* mlp_b1   = (const float*)d_in[11];
    const float* mlp_w2   = (const float*)d_in[12];
    const float* mlp_b2   = (const float*)d_in[13];
    float* out = (float*)d_out;

    cudaFuncSetAttribute(win_attn_kernel,
                         cudaFuncAttributeMaxDynamicSharedMemorySize, A_TOT * 4);
    cudaFuncSetAttribute(mlp_kernel,
                         cudaFuncAttributeMaxDynamicSharedMemorySize, B_TOT * 4);

    win_attn_kernel<<<NTILE, 512, A_TOT * 4>>>(x, norm1_g, norm1_b,
                                               qkv_w, qkv_b, proj_w, proj_b,
                                               bias_tab);
    mlp_kernel<<<NTILE, 512, B_TOT * 4>>>(norm2_g, norm2_b,
                                          mlp_w1, mlp_b1, mlp_w2, mlp_b2, out);
}